// round 13
// baseline (speedup 1.0000x reference)
#include <cuda_runtime.h>
#include <math.h>
#include <stdint.h>

#define Nn 20000
#define Ee 320000
#define ENt 340000
#define Gg 128
#define Dd 256
#define EDd 64
#define LDB 512

// ---------------- static scratch ----------------
__device__ float g_h0[Nn*Dd];
__device__ float g_eA[Ee*EDd];
__device__ float g_eB[Ee*EDd];
__device__ float g_loope[Nn*EDd];
__device__ float g_big[Nn*LDB];          // [xl | xr] stride 512
__device__ float g_pq[Nn*128];           // [P | Q] stride 128
__device__ float g_logits[ENt*4];
__device__ float g_hjk[Nn*Dd*4];
__device__ float g_hfin[Nn*Dd];
__device__ float g_gate[Nn];
__device__ float g_wpack[4*Dd*LDB];
__device__ float g_bpack[4*LDB];
__device__ float g_wpq[4*Dd*128];
__device__ int   g_deg[Nn];
__device__ int   g_rowptr[Nn+1];
__device__ int   g_fill[Nn];
__device__ int   g_csr[ENt];
__device__ int   g_srcx[ENt];
__device__ int   g_dstx[ENt];
__device__ int   g_bsum[20];

__device__ __forceinline__ float siluf(float v){ return v/(1.f+__expf(-v)); }

__device__ __forceinline__ uint32_t f2tf32(float f){
    uint32_t r;
    asm("cvt.rna.tf32.f32 %0, %1;" : "=r"(r) : "f"(f));
    return r;
}

// ---------------- init / encoders / packing ----------------
__global__ void k_zero_deg(){
    int i = blockIdx.x*blockDim.x + threadIdx.x;
    if(i < Nn) g_deg[i] = 0;
}

__global__ void k_atom_enc(const float* __restrict__ x, const float* __restrict__ W,
                           const float* __restrict__ b){
    int idx = blockIdx.x*blockDim.x + threadIdx.x;
    if(idx >= Nn*Dd) return;
    int n = idx >> 8, c = idx & 255;
    float acc = b[c];
#pragma unroll
    for(int k=0;k<9;k++) acc += x[n*9+k]*W[k*Dd+c];
    g_h0[idx] = acc;
}

__global__ void k_bond_enc(const float* __restrict__ ea, const float* __restrict__ W,
                           const float* __restrict__ b){
    int idx = blockIdx.x*blockDim.x + threadIdx.x;
    if(idx >= Ee*EDd) return;
    int e = idx >> 6, c = idx & 63;
    float acc = b[c];
#pragma unroll
    for(int k=0;k<3;k++) acc += ea[e*3+k]*W[k*EDd+c];
    g_eA[idx] = acc;
}

__global__ void k_pack(const float* __restrict__ Wl, const float* __restrict__ Wr){
    int idx = blockIdx.x*blockDim.x + threadIdx.x;
    if(idx >= 4*Dd*LDB) return;
    int l = idx/(Dd*LDB);
    int r = (idx/LDB)%Dd;
    int n = idx%LDB;
    g_wpack[idx] = (n < 256) ? Wl[l*65536 + r*256 + n] : Wr[l*65536 + r*256 + (n-256)];
}

__global__ void k_packpq(const float* __restrict__ eW){
    int idx = blockIdx.x*blockDim.x + threadIdx.x;
    if(idx >= 4*Dd*128) return;
    int l = idx/(Dd*128);
    int r = (idx/128)%Dd;
    int n = idx%128;
    g_wpq[idx] = (n < 64) ? eW[l*36864 + r*64 + n] : eW[l*36864 + (256+r)*64 + (n-64)];
}

__global__ void k_packb(const float* __restrict__ bl, const float* __restrict__ br){
    int idx = blockIdx.x*blockDim.x + threadIdx.x;
    if(idx >= 4*LDB) return;
    int l = idx/LDB, n = idx%LDB;
    g_bpack[idx] = (n<256) ? bl[l*256+n] : br[l*256+(n-256)];
}

__global__ void k_extidx(const int* __restrict__ src, const int* __restrict__ dst){
    int i = blockIdx.x*blockDim.x + threadIdx.x;
    if(i >= ENt) return;
    if(i < Ee){ g_srcx[i] = src[i]; g_dstx[i] = dst[i]; }
    else      { g_srcx[i] = g_dstx[i] = i - Ee; }
}

// ---------------- CSR by dst (multi-block scan) ----------------
__global__ void k_deg(const int* __restrict__ dst){
    int e = blockIdx.x*blockDim.x + threadIdx.x;
    if(e < Ee) atomicAdd(&g_deg[dst[e]], 1);
}

__global__ void k_scan_local(){
    __shared__ int sd[1024];
    int b = blockIdx.x, tid = threadIdx.x;
    int i = b*1024 + tid;
    int v = (i < Nn) ? (g_deg[i] + 1) : 0;
    sd[tid] = v; __syncthreads();
    for(int off=1; off<1024; off<<=1){
        int t = (tid >= off) ? sd[tid-off] : 0;
        __syncthreads();
        sd[tid] += t; __syncthreads();
    }
    if(i < Nn) g_rowptr[i+1] = sd[tid];
    if(tid == 1023) g_bsum[b] = sd[1023];
}

__global__ void k_scan_off(){
    if(threadIdx.x == 0){
        int acc = 0;
        for(int b=0;b<20;b++){ int t = g_bsum[b]; g_bsum[b] = acc; acc += t; }
        g_rowptr[0] = 0;
    }
}

__global__ void k_scan_add(){
    int i = blockIdx.x*blockDim.x + threadIdx.x;
    if(i < Nn){
        int r = g_rowptr[i+1] + g_bsum[i>>10];
        g_rowptr[i+1] = r;
        g_fill[i] = r - (g_deg[i] + 1);
    }
}

__global__ void k_fill(const int* __restrict__ dst){
    int e = blockIdx.x*blockDim.x + threadIdx.x;
    if(e < Ee){ int p = atomicAdd(&g_fill[dst[e]], 1); g_csr[p] = e; }
}

__global__ void k_selfloop(){
    int n = blockIdx.x*blockDim.x + threadIdx.x;
    if(n < Nn) g_csr[g_rowptr[n+1]-1] = Ee + n;
}

__global__ void k_loope(const float* __restrict__ e){
    int n = blockIdx.x;
    int tid = threadIdx.x;           // 64 threads
    int b = g_rowptr[n];
    int cnt = g_rowptr[n+1] - 1 - b;
    float acc = 0.f;
    for(int j=0;j<cnt;j++){
        int eid = g_csr[b+j];
        acc += e[(size_t)eid*EDd + tid];
    }
    g_loope[n*EDd + tid] = acc / (float)max(cnt, 1);
}

// ---------------- tf32 tensor-core GEMM, double-buffered (K > BK) ----------------
// GMODE: 0 = plain A; 1 = rows < Ee from A, rows >= Ee from g_loope
// EPI: 0 = +bias; 1 = +bias+silu; 5 = gate epilogue; 6 = accumulate+silu (split-K p2)
template<int BM,int BN,int BK,int WM,int WN,int GMODE,int EPI>
__global__ void mma_gemm(const float* __restrict__ A, int lda,
                         const float* __restrict__ B, int ldb,
                         const float* __restrict__ bias,
                         float* __restrict__ C, int ldc,
                         int M, int K,
                         const float* __restrict__ aux1,
                         const float* __restrict__ aux2,
                         const int* __restrict__ srcv, const int* __restrict__ dstv,
                         const float* __restrict__ lns, const float* __restrict__ lnb,
                         int ldx)
{
    constexpr int WARPS_N = BN/WN, WARPS_M = BM/WM;
    constexpr int NTHREADS = WARPS_M*WARPS_N*32;
    constexpr int MT = WM/16, NT2 = WN/8;
    constexpr int PAD = 8;
    __shared__ uint32_t As[2][BK][BM+PAD];
    __shared__ uint32_t Bs[2][BK][BN+PAD];
    __shared__ float sEp[(EPI==5)?4*BM:1];

    int tid = threadIdx.x;
    int m0 = blockIdx.y*BM, n0 = blockIdx.x*BN;

    int warp = tid>>5, lane = tid&31;
    int warp_n = warp % WARPS_N, warp_m = warp / WARPS_N;
    int wm0 = warp_m*WM, wn0 = warp_n*WN;
    int g = lane>>2, tg = lane&3;

    float acc[MT][NT2][4];
#pragma unroll
    for(int i=0;i<MT;i++)
#pragma unroll
        for(int j=0;j<NT2;j++)
#pragma unroll
            for(int q=0;q<4;q++) acc[i][j][q] = 0.f;

    constexpr int AV = (BM*BK/4)/NTHREADS;
    constexpr int BV = (BK*BN/4)/NTHREADS;
    float4 ra[AV], rb[BV];

    auto load_g = [&](int k0){
#pragma unroll
        for(int it=0; it<AV; it++){
            int u = tid + it*NTHREADS;
            int r = u/(BK/4), kq = u%(BK/4);
            int k = k0 + kq*4;
            int grow = m0 + r;
            float4 v;
            if(GMODE == 1){
                if(grow < Ee)       v = *(const float4*)(A + (size_t)grow*64 + k);
                else if(grow < M)   v = *(const float4*)(g_loope + (size_t)(grow-Ee)*64 + k);
                else                v = make_float4(0.f,0.f,0.f,0.f);
            } else {
                if(grow < M) v = *(const float4*)(A + (size_t)grow*lda + k);
                else         v = make_float4(0.f,0.f,0.f,0.f);
            }
            ra[it] = v;
        }
#pragma unroll
        for(int it=0; it<BV; it++){
            int u = tid + it*NTHREADS;
            int kk = u/(BN/4), cq = u%(BN/4);
            rb[it] = *(const float4*)(B + (size_t)(k0+kk)*ldb + n0 + cq*4);
        }
    };
    auto store_s = [&](int buf){
#pragma unroll
        for(int it=0; it<AV; it++){
            int u = tid + it*NTHREADS;
            int r = u/(BK/4), kq = u%(BK/4);
            As[buf][kq*4+0][r]=f2tf32(ra[it].x); As[buf][kq*4+1][r]=f2tf32(ra[it].y);
            As[buf][kq*4+2][r]=f2tf32(ra[it].z); As[buf][kq*4+3][r]=f2tf32(ra[it].w);
        }
#pragma unroll
        for(int it=0; it<BV; it++){
            int u = tid + it*NTHREADS;
            int kk = u/(BN/4), cq = u%(BN/4);
            Bs[buf][kk][cq*4+0]=f2tf32(rb[it].x); Bs[buf][kk][cq*4+1]=f2tf32(rb[it].y);
            Bs[buf][kk][cq*4+2]=f2tf32(rb[it].z); Bs[buf][kk][cq*4+3]=f2tf32(rb[it].w);
        }
    };

    load_g(0);
    store_s(0);
    __syncthreads();

    int T = K/BK;
    for(int kt=0; kt<T; kt++){
        if(kt+1 < T) load_g((kt+1)*BK);
        int buf = kt & 1;
#pragma unroll
        for(int ks=0; ks<BK/8; ks++){
            uint32_t af[MT][4], bf[NT2][2];
#pragma unroll
            for(int mt=0; mt<MT; mt++){
                int row = wm0 + mt*16 + g;
                af[mt][0] = As[buf][ks*8+tg  ][row];
                af[mt][1] = As[buf][ks*8+tg  ][row+8];
                af[mt][2] = As[buf][ks*8+tg+4][row];
                af[mt][3] = As[buf][ks*8+tg+4][row+8];
            }
#pragma unroll
            for(int nt=0; nt<NT2; nt++){
                int col = wn0 + nt*8 + g;
                bf[nt][0] = Bs[buf][ks*8+tg  ][col];
                bf[nt][1] = Bs[buf][ks*8+tg+4][col];
            }
#pragma unroll
            for(int mt=0; mt<MT; mt++)
#pragma unroll
                for(int nt=0; nt<NT2; nt++){
                    asm volatile(
                        "mma.sync.aligned.m16n8k8.row.col.f32.tf32.tf32.f32 "
                        "{%0,%1,%2,%3}, {%4,%5,%6,%7}, {%8,%9}, {%0,%1,%2,%3};"
                        : "+f"(acc[mt][nt][0]), "+f"(acc[mt][nt][1]),
                          "+f"(acc[mt][nt][2]), "+f"(acc[mt][nt][3])
                        : "r"(af[mt][0]), "r"(af[mt][1]), "r"(af[mt][2]), "r"(af[mt][3]),
                          "r"(bf[nt][0]), "r"(bf[nt][1]));
                }
        }
        if(kt+1 < T){
            store_s((kt+1)&1);
            __syncthreads();
        }
    }

    if(EPI == 5){
        float p0[MT], p1[MT];
#pragma unroll
        for(int mt=0; mt<MT; mt++){ p0[mt]=0.f; p1[mt]=0.f; }
#pragma unroll
        for(int mt=0; mt<MT; mt++){
#pragma unroll
            for(int nt=0; nt<NT2; nt++){
                int col = wn0 + nt*8 + 2*tg;
                float b0 = bias[col], b1 = bias[col+1];
                float w0 = lns[col],  w1 = lns[col+1];
                float v0 = siluf(acc[mt][nt][0]+b0);
                float v1 = siluf(acc[mt][nt][1]+b1);
                float v2 = siluf(acc[mt][nt][2]+b0);
                float v3 = siluf(acc[mt][nt][3]+b1);
                p0[mt] += v0*w0 + v1*w1;
                p1[mt] += v2*w0 + v3*w1;
            }
        }
#pragma unroll
        for(int mt=0; mt<MT; mt++){
            p0[mt] += __shfl_xor_sync(0xffffffffu, p0[mt], 1);
            p0[mt] += __shfl_xor_sync(0xffffffffu, p0[mt], 2);
            p1[mt] += __shfl_xor_sync(0xffffffffu, p1[mt], 1);
            p1[mt] += __shfl_xor_sync(0xffffffffu, p1[mt], 2);
            if(tg == 0){
                int rr0 = wm0 + mt*16 + g;
                sEp[warp_n*BM + rr0]     = p0[mt];
                sEp[warp_n*BM + rr0 + 8] = p1[mt];
            }
        }
        __syncthreads();
        if(tid < BM){
            int grow = m0 + tid;
            if(grow < M){
                float v = 0.f;
#pragma unroll
                for(int wn = 0; wn < WARPS_N; wn++) v += sEp[wn*BM + tid];
                g_gate[grow] = v + lnb[0];
            }
        }
    } else if(EPI == 6){
#pragma unroll
        for(int mt=0; mt<MT; mt++){
#pragma unroll
            for(int nt=0; nt<NT2; nt++){
                int col = n0 + wn0 + nt*8 + 2*tg;
                int row0 = m0 + wm0 + mt*16 + g;
                if(row0 < M){
                    size_t ro = (size_t)row0*ldc + col;
                    C[ro]   = siluf(acc[mt][nt][0] + C[ro]);
                    C[ro+1] = siluf(acc[mt][nt][1] + C[ro+1]);
                }
                int row1 = row0 + 8;
                if(row1 < M){
                    size_t ro = (size_t)row1*ldc + col;
                    C[ro]   = siluf(acc[mt][nt][2] + C[ro]);
                    C[ro+1] = siluf(acc[mt][nt][3] + C[ro+1]);
                }
            }
        }
    } else {
#pragma unroll
        for(int mt=0; mt<MT; mt++){
#pragma unroll
            for(int nt=0; nt<NT2; nt++){
                int col = n0 + wn0 + nt*8 + 2*tg;
                float b0 = bias? bias[col]   : 0.f;
                float b1 = bias? bias[col+1] : 0.f;
                int row0 = m0 + wm0 + mt*16 + g;
                if(row0 < M){
                    float v0 = acc[mt][nt][0] + b0;
                    float v1 = acc[mt][nt][1] + b1;
                    if(EPI==1){ v0 = siluf(v0); v1 = siluf(v1); }
                    C[(size_t)row0*ldc + col]   = v0;
                    C[(size_t)row0*ldc + col+1] = v1;
                }
                int row1 = row0 + 8;
                if(row1 < M){
                    float v2 = acc[mt][nt][2] + b0;
                    float v3 = acc[mt][nt][3] + b1;
                    if(EPI==1){ v2 = siluf(v2); v3 = siluf(v3); }
                    C[(size_t)row1*ldc + col]   = v2;
                    C[(size_t)row1*ldc + col+1] = v3;
                }
            }
        }
    }
}

// ---------------- single-stage tf32 GEMM for K == BK (dynamic smem) ----------------
// EPI: 3 = logits epilogue -> C=[M,4];  4 = edge MLP epilogue (silu+LN64)
template<int BM,int BN,int BK,int WM,int WN,int GMODE,int EPI>
__global__ void mma_gemm1(const float* __restrict__ A, int lda,
                          const float* __restrict__ B, int ldb,
                          const float* __restrict__ bias,
                          float* __restrict__ C, int ldc,
                          int M,
                          const float* __restrict__ aux1,
                          const float* __restrict__ aux2,
                          const int* __restrict__ srcv, const int* __restrict__ dstv,
                          const float* __restrict__ lns, const float* __restrict__ lnb,
                          int ldx)
{
    constexpr int WARPS_N = BN/WN, WARPS_M = BM/WM;
    constexpr int NTHREADS = WARPS_M*WARPS_N*32;
    constexpr int MT = WM/16, NT2 = WN/8;
    constexpr int PAD = 8;
    extern __shared__ uint32_t dsm[];
    uint32_t (*As)[BM+PAD] = reinterpret_cast<uint32_t(*)[BM+PAD]>(dsm);
    uint32_t (*Bs)[BN+PAD] = reinterpret_cast<uint32_t(*)[BN+PAD]>(dsm + BK*(BM+PAD));
    int*   sSrc = (int*)(dsm + BK*(BM+PAD) + BK*(BN+PAD));
    int*   sDst = sSrc + BM;
    float* sEp  = (float*)(sDst + BM);     // 4*BM floats

    int tid = threadIdx.x;
    int m0 = blockIdx.y*BM, n0 = blockIdx.x*BN;

    for(int t=tid; t<BM; t+=NTHREADS){
        int r = m0 + t;
        sSrc[t] = (r < M) ? srcv[r] : 0;
        sDst[t] = (r < M) ? dstv[r] : 0;
    }

    constexpr int AV = (BM*BK/4)/NTHREADS;
#pragma unroll
    for(int it=0; it<AV; it++){
        int u = tid + it*NTHREADS;
        int r = u/(BK/4), kq = u%(BK/4);
        int k = kq*4;
        int grow = m0 + r;
        float4 v;
        if(GMODE == 1){
            if(grow < Ee)       v = *(const float4*)(A + (size_t)grow*64 + k);
            else if(grow < M)   v = *(const float4*)(g_loope + (size_t)(grow-Ee)*64 + k);
            else                v = make_float4(0.f,0.f,0.f,0.f);
        } else {
            if(grow < M) v = *(const float4*)(A + (size_t)grow*lda + k);
            else         v = make_float4(0.f,0.f,0.f,0.f);
        }
        As[k+0][r]=f2tf32(v.x); As[k+1][r]=f2tf32(v.y);
        As[k+2][r]=f2tf32(v.z); As[k+3][r]=f2tf32(v.w);
    }
    constexpr int BV = (BK*BN/4)/NTHREADS;
#pragma unroll
    for(int it=0; it<BV; it++){
        int u = tid + it*NTHREADS;
        int kk = u/(BN/4), cq = u%(BN/4);
        float4 v = *(const float4*)(B + (size_t)kk*ldb + n0 + cq*4);
        Bs[kk][cq*4+0]=f2tf32(v.x); Bs[kk][cq*4+1]=f2tf32(v.y);
        Bs[kk][cq*4+2]=f2tf32(v.z); Bs[kk][cq*4+3]=f2tf32(v.w);
    }
    __syncthreads();

    int warp = tid>>5, lane = tid&31;
    int warp_n = warp % WARPS_N, warp_m = warp / WARPS_N;
    int wm0 = warp_m*WM, wn0 = warp_n*WN;
    int g = lane>>2, tg = lane&3;

    float acc[MT][NT2][4];
#pragma unroll
    for(int i=0;i<MT;i++)
#pragma unroll
        for(int j=0;j<NT2;j++)
#pragma unroll
            for(int q=0;q<4;q++) acc[i][j][q] = 0.f;

#pragma unroll
    for(int ks=0; ks<BK/8; ks++){
        uint32_t af[MT][4], bf[NT2][2];
#pragma unroll
        for(int mt=0; mt<MT; mt++){
            int row = wm0 + mt*16 + g;
            af[mt][0] = As[ks*8+tg  ][row];
            af[mt][1] = As[ks*8+tg  ][row+8];
            af[mt][2] = As[ks*8+tg+4][row];
            af[mt][3] = As[ks*8+tg+4][row+8];
        }
#pragma unroll
        for(int nt=0; nt<NT2; nt++){
            int col = wn0 + nt*8 + g;
            bf[nt][0] = Bs[ks*8+tg  ][col];
            bf[nt][1] = Bs[ks*8+tg+4][col];
        }
#pragma unroll
        for(int mt=0; mt<MT; mt++)
#pragma unroll
            for(int nt=0; nt<NT2; nt++){
                asm volatile(
                    "mma.sync.aligned.m16n8k8.row.col.f32.tf32.tf32.f32 "
                    "{%0,%1,%2,%3}, {%4,%5,%6,%7}, {%8,%9}, {%0,%1,%2,%3};"
                    : "+f"(acc[mt][nt][0]), "+f"(acc[mt][nt][1]),
                      "+f"(acc[mt][nt][2]), "+f"(acc[mt][nt][3])
                    : "r"(af[mt][0]), "r"(af[mt][1]), "r"(af[mt][2]), "r"(af[mt][3]),
                      "r"(bf[nt][0]), "r"(bf[nt][1]));
            }
    }

    if(EPI == 3){
        float l0[MT], l1[MT];
#pragma unroll
        for(int mt=0; mt<MT; mt++){ l0[mt]=0.f; l1[mt]=0.f; }
#pragma unroll
        for(int mt=0; mt<MT; mt++){
            int rr0 = wm0 + mt*16 + g, rr1 = rr0 + 8;
            int s0 = sSrc[rr0], d0 = sDst[rr0];
            int s1 = sSrc[rr1], d1 = sDst[rr1];
#pragma unroll
            for(int nt=0; nt<NT2; nt++){
                int gc = n0 + wn0 + nt*8 + 2*tg;
                float a0 = lns[gc], a1 = lns[gc+1];
                float2 xs0 = *(const float2*)&aux1[(size_t)s0*ldx + gc];
                float2 xd0 = *(const float2*)&aux2[(size_t)d0*ldx + gc];
                float2 xs1 = *(const float2*)&aux1[(size_t)s1*ldx + gc];
                float2 xd1 = *(const float2*)&aux2[(size_t)d1*ldx + gc];
                float m00 = acc[mt][nt][0] + xs0.x + xd0.x; m00 = m00>0.f? m00 : 0.2f*m00;
                float m01 = acc[mt][nt][1] + xs0.y + xd0.y; m01 = m01>0.f? m01 : 0.2f*m01;
                float m10 = acc[mt][nt][2] + xs1.x + xd1.x; m10 = m10>0.f? m10 : 0.2f*m10;
                float m11 = acc[mt][nt][3] + xs1.y + xd1.y; m11 = m11>0.f? m11 : 0.2f*m11;
                l0[mt] += m00*a0 + m01*a1;
                l1[mt] += m10*a0 + m11*a1;
            }
        }
#pragma unroll
        for(int mt=0; mt<MT; mt++){
            l0[mt] += __shfl_xor_sync(0xffffffffu, l0[mt], 1);
            l0[mt] += __shfl_xor_sync(0xffffffffu, l0[mt], 2);
            l1[mt] += __shfl_xor_sync(0xffffffffu, l1[mt], 1);
            l1[mt] += __shfl_xor_sync(0xffffffffu, l1[mt], 2);
            if(tg == 0){
                int rr0 = wm0 + mt*16 + g;
                sEp[warp_n*BM + rr0]     = l0[mt];
                sEp[warp_n*BM + rr0 + 8] = l1[mt];
            }
        }
        __syncthreads();
        int row = tid & (BM-1), hh = tid >> 7;
        int grow = m0 + row;
        if(grow < M){
            float v = sEp[(2*hh)*BM + row] + sEp[(2*hh+1)*BM + row];
            C[(size_t)grow*4 + (n0>>6) + hh] = v;
        }
    } else if(EPI == 4){
        float sv[MT][NT2][4];
        float s1a[MT], s2a[MT], s1b[MT], s2b[MT];
#pragma unroll
        for(int mt=0; mt<MT; mt++){ s1a[mt]=s2a[mt]=s1b[mt]=s2b[mt]=0.f; }
#pragma unroll
        for(int mt=0; mt<MT; mt++){
            int rr0 = wm0 + mt*16 + g, rr1 = rr0 + 8;
            int s0 = sSrc[rr0], d0 = sDst[rr0];
            int s1i = sSrc[rr1], d1i = sDst[rr1];
#pragma unroll
            for(int nt=0; nt<NT2; nt++){
                int col = wn0 + nt*8 + 2*tg;
                float b0 = bias[col], b1 = bias[col+1];
                float2 p0 = *(const float2*)&aux1[(size_t)s0*ldx + col];
                float2 q0 = *(const float2*)&aux1[(size_t)d0*ldx + 64 + col];
                float2 p1 = *(const float2*)&aux1[(size_t)s1i*ldx + col];
                float2 q1 = *(const float2*)&aux1[(size_t)d1i*ldx + 64 + col];
                float v0 = siluf(acc[mt][nt][0]+b0+p0.x+q0.x);
                float v1 = siluf(acc[mt][nt][1]+b1+p0.y+q0.y);
                float v2 = siluf(acc[mt][nt][2]+b0+p1.x+q1.x);
                float v3 = siluf(acc[mt][nt][3]+b1+p1.y+q1.y);
                sv[mt][nt][0]=v0; sv[mt][nt][1]=v1; sv[mt][nt][2]=v2; sv[mt][nt][3]=v3;
                s1a[mt]+=v0+v1; s2a[mt]+=v0*v0+v1*v1;
                s1b[mt]+=v2+v3; s2b[mt]+=v2*v2+v3*v3;
            }
        }
#pragma unroll
        for(int mt=0; mt<MT; mt++){
#pragma unroll
            for(int o=1;o<4;o<<=1){
                s1a[mt] += __shfl_xor_sync(0xffffffffu, s1a[mt], o);
                s2a[mt] += __shfl_xor_sync(0xffffffffu, s2a[mt], o);
                s1b[mt] += __shfl_xor_sync(0xffffffffu, s1b[mt], o);
                s2b[mt] += __shfl_xor_sync(0xffffffffu, s2b[mt], o);
            }
            if(tg == 0){
                int r0 = wm0 + mt*16 + g;
                sEp[(warp_n*BM + r0)*2+0]   = s1a[mt];
                sEp[(warp_n*BM + r0)*2+1]   = s2a[mt];
                sEp[(warp_n*BM + r0+8)*2+0] = s1b[mt];
                sEp[(warp_n*BM + r0+8)*2+1] = s2b[mt];
            }
        }
        __syncthreads();
#pragma unroll
        for(int mt=0; mt<MT; mt++){
            int r0 = wm0 + mt*16 + g;
            float t1 = sEp[r0*2+0] + sEp[(BM+r0)*2+0];
            float t2 = sEp[r0*2+1] + sEp[(BM+r0)*2+1];
            float mu0 = t1*(1.f/BN);
            float iv0 = rsqrtf(t2*(1.f/BN)-mu0*mu0 + 1e-5f);
            int r1 = r0+8;
            float u1 = sEp[r1*2+0] + sEp[(BM+r1)*2+0];
            float u2 = sEp[r1*2+1] + sEp[(BM+r1)*2+1];
            float mu1 = u1*(1.f/BN);
            float iv1 = rsqrtf(u2*(1.f/BN)-mu1*mu1 + 1e-5f);
#pragma unroll
            for(int nt=0; nt<NT2; nt++){
                int col = wn0 + nt*8 + 2*tg;
                float g0 = lns[col], g1 = lns[col+1];
                float c0 = lnb[col], c1 = lnb[col+1];
                size_t ro0 = (size_t)(m0+r0)*ldc + col;
                size_t ro1 = (size_t)(m0+r1)*ldc + col;
                C[ro0]   = (sv[mt][nt][0]-mu0)*iv0*g0 + c0;
                C[ro0+1] = (sv[mt][nt][1]-mu0)*iv0*g1 + c1;
                C[ro1]   = (sv[mt][nt][2]-mu1)*iv1*g0 + c0;
                C[ro1+1] = (sv[mt][nt][3]-mu1)*iv1*g1 + c1;
            }
        }
    }
}

// ---------------- per-node softmax + aggregation + bias + silu + LN(256) ----------------
__global__ void k_aggregate(const int* __restrict__ src,
                            const float* __restrict__ xl,
                            const float* __restrict__ bias,
                            const float* __restrict__ ln1s, const float* __restrict__ ln1b,
                            float* __restrict__ out)
{
    __shared__ float sm4[4], sinv[4];
    __shared__ int   sS[32];
    __shared__ float sA[32*4];
    __shared__ float red[16];

    int n = blockIdx.x, tid = threadIdx.x, lane = tid&31, warp = tid>>5;
    int b = g_rowptr[n];
    int cnt = g_rowptr[n+1] - b;

    if(warp == 0){
        float mx[4] = {-1e30f,-1e30f,-1e30f,-1e30f};
        for(int j=lane; j<cnt; j+=32){
            int eid = g_csr[b+j];
#pragma unroll
            for(int h=0;h<4;h++) mx[h] = fmaxf(mx[h], g_logits[eid*4+h]);
        }
#pragma unroll
        for(int h=0;h<4;h++)
            for(int o=16;o;o>>=1) mx[h] = fmaxf(mx[h], __shfl_xor_sync(0xffffffffu, mx[h], o));
        float su[4] = {0.f,0.f,0.f,0.f};
        for(int j=lane; j<cnt; j+=32){
            int eid = g_csr[b+j];
#pragma unroll
            for(int h=0;h<4;h++) su[h] += __expf(g_logits[eid*4+h] - mx[h]);
        }
#pragma unroll
        for(int h=0;h<4;h++)
            for(int o=16;o;o>>=1) su[h] += __shfl_xor_sync(0xffffffffu, su[h], o);
        if(lane < 4){ sm4[lane] = mx[lane]; sinv[lane] = 1.f/(su[lane] + 1e-16f); }
    }
    __syncthreads();

    float a0=0.f, a1=0.f, a2=0.f, a3=0.f;
    int c = tid, h = c>>6;
    for(int base=0; base<cnt; base+=32){
        int jn = min(32, cnt-base);
        if(tid < 32 && lane < jn){
            int eid = g_csr[b+base+lane];
            sS[lane] = (eid < Ee) ? src[eid] : n;
#pragma unroll
            for(int hh=0; hh<4; hh++)
                sA[lane*4+hh] = __expf(g_logits[eid*4+hh] - sm4[hh]) * sinv[hh];
        }
        __syncthreads();
        int j = 0;
        for(; j+4<=jn; j+=4){
            a0 += sA[(j+0)*4+h] * xl[(size_t)sS[j+0]*LDB + c];
            a1 += sA[(j+1)*4+h] * xl[(size_t)sS[j+1]*LDB + c];
            a2 += sA[(j+2)*4+h] * xl[(size_t)sS[j+2]*LDB + c];
            a3 += sA[(j+3)*4+h] * xl[(size_t)sS[j+3]*LDB + c];
        }
        for(; j<jn; j++)
            a0 += sA[j*4+h] * xl[(size_t)sS[j]*LDB + c];
        __syncthreads();
    }
    float acc = (a0+a1)+(a2+a3);

    float v = siluf(acc + bias[c]);
    float s1 = v, s2 = v*v;
    for(int o=16;o;o>>=1){ s1 += __shfl_xor_sync(0xffffffffu,s1,o); s2 += __shfl_xor_sync(0xffffffffu,s2,o); }
    if(lane == 0){ red[warp] = s1; red[8+warp] = s2; }
    __syncthreads();
    if(warp == 0){
        float a = (lane<8)? red[lane]   : 0.f;
        float q = (lane<8)? red[8+lane] : 0.f;
        for(int o=4;o;o>>=1){ a += __shfl_xor_sync(0xffffffffu,a,o); q += __shfl_xor_sync(0xffffffffu,q,o); }
        if(lane == 0){ red[0]=a; red[8]=q; }
    }
    __syncthreads();
    float mu  = red[0]*(1.f/256.f);
    float var = red[8]*(1.f/256.f) - mu*mu;
    out[(size_t)n*1024 + c] = (v-mu)*rsqrtf(var+1e-5f)*ln1s[c] + ln1b[c];
}

// ---------------- LN(256) on g_hfin ----------------
__global__ void k_ln256(const float* __restrict__ s, const float* __restrict__ b){
    __shared__ float red[16];
    int n = blockIdx.x, tid = threadIdx.x, lane = tid&31, warp = tid>>5;
    float v = g_hfin[(size_t)n*256+tid];
    float s1 = v, s2 = v*v;
    for(int o=16;o;o>>=1){ s1 += __shfl_xor_sync(0xffffffffu,s1,o); s2 += __shfl_xor_sync(0xffffffffu,s2,o); }
    if(lane==0){ red[warp]=s1; red[8+warp]=s2; }
    __syncthreads();
    if(warp==0){
        float a = (lane<8)? red[lane]:0.f;
        float q = (lane<8)? red[8+lane]:0.f;
        for(int o=4;o;o>>=1){ a += __shfl_xor_sync(0xffffffffu,a,o); q += __shfl_xor_sync(0xffffffffu,q,o); }
        if(lane==0){ red[0]=a; red[8]=q; }
    }
    __syncthreads();
    float mu = red[0]*(1.f/256.f);
    float var = red[8]*(1.f/256.f)-mu*mu;
    g_hfin[(size_t)n*256+tid] = (v-mu)*rsqrtf(var+1e-5f)*s[tid]+b[tid];
}

// ---------------- per-graph pooling + head ----------------
__global__ void k_pool(const int* __restrict__ batch, const float* __restrict__ hW,
                       const float* __restrict__ hb, float* __restrict__ out){
    __shared__ int bnd[2];
    __shared__ float red[8];
    __shared__ float sstat[2];
    int g = blockIdx.x, tid = threadIdx.x, lane = tid&31, warp = tid>>5;
    if(tid < 2){
        int tgt = g + tid;
        int lo=0, hi=Nn;
        while(lo<hi){ int m=(lo+hi)>>1; if(batch[m]<tgt) lo=m+1; else hi=m; }
        bnd[tid]=lo;
    }
    __syncthreads();
    int lo=bnd[0], hi=bnd[1];

    float m = -1e30f;
    for(int i=lo+tid;i<hi;i+=256) m = fmaxf(m, g_gate[i]);
    for(int o=16;o;o>>=1) m = fmaxf(m, __shfl_xor_sync(0xffffffffu,m,o));
    if(lane==0) red[warp]=m;
    __syncthreads();
    if(tid==0){
        float v=red[0];
        for(int w2=1;w2<8;w2++) v = fmaxf(v, red[w2]);
        if(v < -1e29f) v = 0.f;
        sstat[0]=v;
    }
    __syncthreads();
    m = sstat[0];
    float sd = 0.f;
    for(int i=lo+tid;i<hi;i+=256) sd += __expf(g_gate[i]-m);
    for(int o=16;o;o>>=1) sd += __shfl_xor_sync(0xffffffffu,sd,o);
    if(lane==0) red[warp]=sd;
    __syncthreads();
    if(tid==0){
        float v=0.f;
        for(int w2=0;w2<8;w2++) v += red[w2];
        sstat[1] = 1.f/(v+1e-16f);
    }
    __syncthreads();
    float inv = sstat[1];
    float acc = 0.f;
    for(int i=lo;i<hi;i++){
        float w2 = __expf(g_gate[i]-m)*inv;
        acc += w2 * g_hfin[(size_t)i*256+tid];
    }
    float pv = acc*hW[tid];
    for(int o=16;o;o>>=1) pv += __shfl_xor_sync(0xffffffffu,pv,o);
    if(lane==0) red[warp]=pv;
    __syncthreads();
    if(tid==0){
        float v=0.f;
        for(int w2=0;w2<8;w2++) v += red[w2];
        out[g] = v + hb[0];
    }
}

// ---------------- host ----------------
extern "C" void kernel_launch(void* const* d_in, const int* in_sizes, int n_in,
                              void* d_out, int out_size){
    const float* x     = (const float*)d_in[0];
    const int*   ei    = (const int*)  d_in[1];
    const float* eattr = (const float*)d_in[2];
    const int*   batch = (const int*)  d_in[3];
    const float* atomW = (const float*)d_in[4];
    const float* atomB = (const float*)d_in[5];
    const float* bondW = (const float*)d_in[6];
    const float* bondB = (const float*)d_in[7];
    const float* Wl    = (const float*)d_in[8];
    const float* bl    = (const float*)d_in[9];
    const float* Wr    = (const float*)d_in[10];
    const float* br    = (const float*)d_in[11];
    const float* We    = (const float*)d_in[12];
    const float* att   = (const float*)d_in[13];
    const float* bias  = (const float*)d_in[14];
    const float* ln1s  = (const float*)d_in[15];
    const float* ln1b  = (const float*)d_in[16];
    const float* eW    = (const float*)d_in[17];
    const float* eb    = (const float*)d_in[18];
    const float* ln2s  = (const float*)d_in[19];
    const float* ln2b  = (const float*)d_in[20];
    const float* jkW   = (const float*)d_in[21];
    const float* jkb   = (const float*)d_in[22];
    const float* ln3s  = (const float*)d_in[23];
    const float* ln3b  = (const float*)d_in[24];
    const float* gW1   = (const float*)d_in[25];
    const float* gb1   = (const float*)d_in[26];
    const float* gW2   = (const float*)d_in[27];
    const float* gb2   = (const float*)d_in[28];
    const float* hW    = (const float*)d_in[29];
    const float* hb    = (const float*)d_in[30];
    float* out = (float*)d_out;

    const int* src = ei;
    const int* dst = ei + Ee;

    float *h0p, *eAp, *eBp, *bigp, *pqp, *hjkp, *hfinp, *logp, *wpk, *bpk, *wpq;
    int *srcxp, *dstxp;
    cudaGetSymbolAddress((void**)&h0p,   g_h0);
    cudaGetSymbolAddress((void**)&eAp,   g_eA);
    cudaGetSymbolAddress((void**)&eBp,   g_eB);
    cudaGetSymbolAddress((void**)&bigp,  g_big);
    cudaGetSymbolAddress((void**)&pqp,   g_pq);
    cudaGetSymbolAddress((void**)&hjkp,  g_hjk);
    cudaGetSymbolAddress((void**)&hfinp, g_hfin);
    cudaGetSymbolAddress((void**)&logp,  g_logits);
    cudaGetSymbolAddress((void**)&wpk,   g_wpack);
    cudaGetSymbolAddress((void**)&bpk,   g_bpack);
    cudaGetSymbolAddress((void**)&wpq,   g_wpq);
    cudaGetSymbolAddress((void**)&srcxp, g_srcx);
    cudaGetSymbolAddress((void**)&dstxp, g_dstx);

    const int LOG1_SMEM  = (64*136 + 64*136 + 128 + 128 + 512)*4;  // 72704
    const int EDGE1_SMEM = (64*136 + 64*72  + 128 + 128 + 512)*4;  // 56320
    cudaFuncSetAttribute(mma_gemm1<128,128,64,64,32,1,3>,
                         cudaFuncAttributeMaxDynamicSharedMemorySize, LOG1_SMEM);
    cudaFuncSetAttribute(mma_gemm1<128,64,64,32,32,0,4>,
                         cudaFuncAttributeMaxDynamicSharedMemorySize, EDGE1_SMEM);

    static cudaStream_t s2 = nullptr;
    static cudaEvent_t evFork, evP, evCSR, evJK1, evL[4], evA[3];
    if(!s2){
        cudaStreamCreateWithFlags(&s2, cudaStreamNonBlocking);
        cudaEventCreateWithFlags(&evFork, cudaEventDisableTiming);
        cudaEventCreateWithFlags(&evP,    cudaEventDisableTiming);
        cudaEventCreateWithFlags(&evCSR,  cudaEventDisableTiming);
        cudaEventCreateWithFlags(&evJK1,  cudaEventDisableTiming);
        for(int i=0;i<4;i++) cudaEventCreateWithFlags(&evL[i], cudaEventDisableTiming);
        for(int i=0;i<3;i++) cudaEventCreateWithFlags(&evA[i], cudaEventDisableTiming);
    }

    // ---- fork s2 ----
    cudaEventRecord(evFork, 0);
    cudaStreamWaitEvent(s2, evFork, 0);

    // s2: encoders + packing + extidx
    k_atom_enc<<<(Nn*Dd+255)/256,256,0,s2>>>(x, atomW, atomB);
    k_bond_enc<<<(Ee*EDd+255)/256,256,0,s2>>>(eattr, bondW, bondB);
    k_pack<<<(4*Dd*LDB+255)/256,256,0,s2>>>(Wl, Wr);
    k_packpq<<<(4*Dd*128+255)/256,256,0,s2>>>(eW);
    k_packb<<<(4*LDB+255)/256,256,0,s2>>>(bl, br);
    k_extidx<<<(ENt+255)/256,256,0,s2>>>(src, dst);
    cudaEventRecord(evP, s2);

    // s1: CSR build with multi-block scan
    k_zero_deg<<<(Nn+255)/256,256>>>();
    k_deg <<<(Ee+255)/256,256>>>(dst);
    k_scan_local<<<20,1024>>>();
    k_scan_off<<<1,32>>>();
    k_scan_add<<<(Nn+255)/256,256>>>();
    k_fill<<<(Ee+255)/256,256>>>(dst);
    k_selfloop<<<(Nn+255)/256,256>>>();
    cudaEventRecord(evCSR, 0);

    // s2: loope(0)
    cudaStreamWaitEvent(s2, evCSR, 0);
    k_loope<<<Nn,64,0,s2>>>(eAp);
    cudaEventRecord(evL[0], s2);

    cudaStreamWaitEvent(0, evP, 0);

    for(int l=0; l<4; l++){
        float* e_cur  = (l&1) ? eBp : eAp;
        float* e_next = (l&1) ? eAp : eBp;
        const float* hcur = (l==0) ? h0p : (hjkp + (l-1)*256);
        int ldh = (l==0) ? 256 : 1024;

        // s1: packed node GEMM [xl|xr] = hcur @ [Wl|Wr]
        dim3 gN(LDB/128, (Nn+127)/128);
        mma_gemm<128,128,16,64,32,0,0><<<gN,256>>>(
            hcur, ldh, wpk + l*Dd*LDB, LDB, bpk + l*LDB, bigp, LDB, Nn, 256,
            nullptr,nullptr,nullptr,nullptr, nullptr,nullptr, 0);

        cudaStreamWaitEvent(0, evL[l], 0);

        // s1: logits (single-stage K=64)
        dim3 gL(2,(ENt+127)/128);
        mma_gemm1<128,128,64,64,32,1,3><<<gL,256,LOG1_SMEM>>>(
            e_cur, 64, We + l*EDd*Dd, 256, nullptr, logp, 4, ENt,
            bigp, bigp + 256, srcxp, dstxp, att + l*256, nullptr, LDB);

        // s1: aggregate
        k_aggregate<<<Nn,256>>>(src, bigp, bias + l*256, ln1s + l*256, ln1b + l*256,
                                hjkp + l*256);

        if(l < 3){
            cudaEventRecord(evA[l], 0);
            // s2: edge path
            cudaStreamWaitEvent(s2, evA[l], 0);
            dim3 gPQ(1,(Nn+127)/128);
            mma_gemm<128,128,16,64,32,0,0><<<gPQ,256,0,s2>>>(
                hjkp + l*256, 1024, wpq + l*Dd*128, 128, nullptr, pqp, 128, Nn, 256,
                nullptr,nullptr,nullptr,nullptr, nullptr,nullptr, 0);
            dim3 gE(1, Ee/128);
            mma_gemm1<128,64,64,32,32,0,4><<<gE,256,EDGE1_SMEM,s2>>>(
                e_cur, 64, eW + l*576*64 + 512*64, 64, eb + l*64, e_next, 64, Ee,
                pqp, nullptr, src, dst, ln2s + l*64, ln2b + l*64, 128);
            k_loope<<<Nn,64,0,s2>>>(e_next);
            cudaEventRecord(evL[l+1], s2);

            if(l == 2){
                dim3 gJK1(2,(Nn+127)/128);
                mma_gemm<128,128,16,64,32,0,0><<<gJK1,256,0,s2>>>(
                    hjkp, 1024, jkW, 256, jkb, hfinp, 256, Nn, 768,
                    nullptr,nullptr,nullptr,nullptr, nullptr,nullptr, 0);
                cudaEventRecord(evJK1, s2);
            }
        }
    }

    // s1: JK split-K part 2
    cudaStreamWaitEvent(0, evJK1, 0);
    dim3 gJK2(2,(Nn+127)/128);
    mma_gemm<128,128,16,64,32,0,6><<<gJK2,256>>>(
        hjkp + 768, 1024, jkW + 768*256, 256, nullptr, hfinp, 256, Nn, 256,
        nullptr,nullptr,nullptr,nullptr, nullptr,nullptr, 0);
    k_ln256<<<Nn,256>>>(ln3s, ln3b);

    dim3 gG1(1,(Nn+127)/128);
    mma_gemm<128,128,16,64,32,0,5><<<gG1,256>>>(
        hfinp, 256, gW1, 128, gb1, nullptr, 0, Nn, 256,
        nullptr,nullptr,nullptr,nullptr, gW2, gb2, 0);

    k_pool<<<Gg,256>>>(batch, hW, hb, out);
}

// round 14
// speedup vs baseline: 1.1094x; 1.1094x over previous
#include <cuda_runtime.h>
#include <math.h>
#include <stdint.h>

#define Nn 20000
#define Ee 320000
#define ENt 340000
#define Gg 128
#define Dd 256
#define EDd 64
#define LDB 512

// ---------------- static scratch ----------------
__device__ float g_h0[Nn*Dd];
__device__ float g_eA[Ee*EDd];
__device__ float g_eB[Ee*EDd];
__device__ float g_loope[Nn*EDd];
__device__ float g_big[Nn*LDB];          // [xl | xr] stride 512
__device__ float g_pq[Nn*128];           // [P | Q] stride 128
__device__ float g_logits[ENt*4];
__device__ float g_hjk[Nn*Dd*4];
__device__ float g_hfin[Nn*Dd];
__device__ float g_gate[Nn];
__device__ float g_wpack[4*Dd*LDB];
__device__ float g_bpack[4*LDB];
__device__ float g_wpq[4*Dd*128];
__device__ int   g_deg[Nn];
__device__ int   g_rowptr[Nn+1];
__device__ int   g_fill[Nn];
__device__ int   g_csr[ENt];
__device__ int   g_srcx[ENt];
__device__ int   g_dstx[ENt];
__device__ int   g_bsum[20];

__device__ __forceinline__ float siluf(float v){ return v/(1.f+__expf(-v)); }

__device__ __forceinline__ uint32_t f2tf32(float f){
    uint32_t r;
    asm("cvt.rna.tf32.f32 %0, %1;" : "=r"(r) : "f"(f));
    return r;
}

// ---------------- init / encoders / packing ----------------
__global__ void k_zero_deg(){
    int i = blockIdx.x*blockDim.x + threadIdx.x;
    if(i < Nn) g_deg[i] = 0;
}

__global__ void k_atom_enc(const float* __restrict__ x, const float* __restrict__ W,
                           const float* __restrict__ b){
    int idx = blockIdx.x*blockDim.x + threadIdx.x;
    if(idx >= Nn*Dd) return;
    int n = idx >> 8, c = idx & 255;
    float acc = b[c];
#pragma unroll
    for(int k=0;k<9;k++) acc += x[n*9+k]*W[k*Dd+c];
    g_h0[idx] = acc;
}

__global__ void k_bond_enc(const float* __restrict__ ea, const float* __restrict__ W,
                           const float* __restrict__ b){
    int idx = blockIdx.x*blockDim.x + threadIdx.x;
    if(idx >= Ee*EDd) return;
    int e = idx >> 6, c = idx & 63;
    float acc = b[c];
#pragma unroll
    for(int k=0;k<3;k++) acc += ea[e*3+k]*W[k*EDd+c];
    g_eA[idx] = acc;
}

__global__ void k_pack(const float* __restrict__ Wl, const float* __restrict__ Wr){
    int idx = blockIdx.x*blockDim.x + threadIdx.x;
    if(idx >= 4*Dd*LDB) return;
    int l = idx/(Dd*LDB);
    int r = (idx/LDB)%Dd;
    int n = idx%LDB;
    g_wpack[idx] = (n < 256) ? Wl[l*65536 + r*256 + n] : Wr[l*65536 + r*256 + (n-256)];
}

__global__ void k_packpq(const float* __restrict__ eW){
    int idx = blockIdx.x*blockDim.x + threadIdx.x;
    if(idx >= 4*Dd*128) return;
    int l = idx/(Dd*128);
    int r = (idx/128)%Dd;
    int n = idx%128;
    g_wpq[idx] = (n < 64) ? eW[l*36864 + r*64 + n] : eW[l*36864 + (256+r)*64 + (n-64)];
}

__global__ void k_packb(const float* __restrict__ bl, const float* __restrict__ br){
    int idx = blockIdx.x*blockDim.x + threadIdx.x;
    if(idx >= 4*LDB) return;
    int l = idx/LDB, n = idx%LDB;
    g_bpack[idx] = (n<256) ? bl[l*256+n] : br[l*256+(n-256)];
}

__global__ void k_extidx(const int* __restrict__ src, const int* __restrict__ dst){
    int i = blockIdx.x*blockDim.x + threadIdx.x;
    if(i >= ENt) return;
    if(i < Ee){ g_srcx[i] = src[i]; g_dstx[i] = dst[i]; }
    else      { g_srcx[i] = g_dstx[i] = i - Ee; }
}

// ---------------- CSR by dst (multi-block scan) ----------------
__global__ void k_deg(const int* __restrict__ dst){
    int e = blockIdx.x*blockDim.x + threadIdx.x;
    if(e < Ee) atomicAdd(&g_deg[dst[e]], 1);
}

__global__ void k_scan_local(){
    __shared__ int sd[1024];
    int b = blockIdx.x, tid = threadIdx.x;
    int i = b*1024 + tid;
    int v = (i < Nn) ? (g_deg[i] + 1) : 0;
    sd[tid] = v; __syncthreads();
    for(int off=1; off<1024; off<<=1){
        int t = (tid >= off) ? sd[tid-off] : 0;
        __syncthreads();
        sd[tid] += t; __syncthreads();
    }
    if(i < Nn) g_rowptr[i+1] = sd[tid];
    if(tid == 1023) g_bsum[b] = sd[1023];
}

__global__ void k_scan_off(){
    if(threadIdx.x == 0){
        int acc = 0;
        for(int b=0;b<20;b++){ int t = g_bsum[b]; g_bsum[b] = acc; acc += t; }
        g_rowptr[0] = 0;
    }
}

__global__ void k_scan_add(){
    int i = blockIdx.x*blockDim.x + threadIdx.x;
    if(i < Nn){
        int r = g_rowptr[i+1] + g_bsum[i>>10];
        g_rowptr[i+1] = r;
        g_fill[i] = r - (g_deg[i] + 1);
    }
}

__global__ void k_fill(const int* __restrict__ dst){
    int e = blockIdx.x*blockDim.x + threadIdx.x;
    if(e < Ee){ int p = atomicAdd(&g_fill[dst[e]], 1); g_csr[p] = e; }
}

__global__ void k_selfloop(){
    int n = blockIdx.x*blockDim.x + threadIdx.x;
    if(n < Nn) g_csr[g_rowptr[n+1]-1] = Ee + n;
}

__global__ void k_loope(const float* __restrict__ e){
    int n = blockIdx.x;
    int tid = threadIdx.x;           // 64 threads
    int b = g_rowptr[n];
    int cnt = g_rowptr[n+1] - 1 - b;
    float acc = 0.f;
    for(int j=0;j<cnt;j++){
        int eid = g_csr[b+j];
        acc += e[(size_t)eid*EDd + tid];
    }
    g_loope[n*EDd + tid] = acc / (float)max(cnt, 1);
}

// ---------------- tf32 tensor-core GEMM, double-buffered ----------------
// GMODE: 0 = plain A; 1 = rows < Ee from A, rows >= Ee from g_loope
// EPI: 0 = +bias; 1 = +bias+silu
//      3 = GATv2 logits epilogue -> C=[M,4]
//      4 = edge MLP epilogue (silu+LN64)
//      5 = gate epilogue -> g_gate[row]
template<int BM,int BN,int BK,int WM,int WN,int GMODE,int EPI>
__global__ void mma_gemm(const float* __restrict__ A, int lda,
                         const float* __restrict__ B, int ldb,
                         const float* __restrict__ bias,
                         float* __restrict__ C, int ldc,
                         int M, int K,
                         const float* __restrict__ aux1,
                         const float* __restrict__ aux2,
                         const int* __restrict__ srcv, const int* __restrict__ dstv,
                         const float* __restrict__ lns, const float* __restrict__ lnb,
                         int ldx)
{
    constexpr int WARPS_N = BN/WN, WARPS_M = BM/WM;
    constexpr int NTHREADS = WARPS_M*WARPS_N*32;
    constexpr int MT = WM/16, NT2 = WN/8;
    constexpr int PAD = 8;
    __shared__ uint32_t As[2][BK][BM+PAD];
    __shared__ uint32_t Bs[2][BK][BN+PAD];
    __shared__ int sSrc[(EPI==3||EPI==4)?BM:1];
    __shared__ int sDst[(EPI==3||EPI==4)?BM:1];
    __shared__ float sEp[(EPI>=3)?4*BM:1];

    int tid = threadIdx.x;
    int m0 = blockIdx.y*BM, n0 = blockIdx.x*BN;

    if(EPI == 3 || EPI == 4){
        for(int t=tid; t<BM; t+=NTHREADS){
            int r = m0 + t;
            sSrc[t] = (r < M) ? srcv[r] : 0;
            sDst[t] = (r < M) ? dstv[r] : 0;
        }
        __syncthreads();
    }

    int warp = tid>>5, lane = tid&31;
    int warp_n = warp % WARPS_N, warp_m = warp / WARPS_N;
    int wm0 = warp_m*WM, wn0 = warp_n*WN;
    int g = lane>>2, tg = lane&3;

    float acc[MT][NT2][4];
#pragma unroll
    for(int i=0;i<MT;i++)
#pragma unroll
        for(int j=0;j<NT2;j++)
#pragma unroll
            for(int q=0;q<4;q++) acc[i][j][q] = 0.f;

    constexpr int AV = (BM*BK/4)/NTHREADS;
    constexpr int BV = (BK*BN/4)/NTHREADS;
    float4 ra[AV], rb[BV];

    auto load_g = [&](int k0){
#pragma unroll
        for(int it=0; it<AV; it++){
            int u = tid + it*NTHREADS;
            int r = u/(BK/4), kq = u%(BK/4);
            int k = k0 + kq*4;
            int grow = m0 + r;
            float4 v;
            if(GMODE == 1){
                if(grow < Ee)       v = *(const float4*)(A + (size_t)grow*64 + k);
                else if(grow < M)   v = *(const float4*)(g_loope + (size_t)(grow-Ee)*64 + k);
                else                v = make_float4(0.f,0.f,0.f,0.f);
            } else {
                if(grow < M) v = *(const float4*)(A + (size_t)grow*lda + k);
                else         v = make_float4(0.f,0.f,0.f,0.f);
            }
            ra[it] = v;
        }
#pragma unroll
        for(int it=0; it<BV; it++){
            int u = tid + it*NTHREADS;
            int kk = u/(BN/4), cq = u%(BN/4);
            rb[it] = *(const float4*)(B + (size_t)(k0+kk)*ldb + n0 + cq*4);
        }
    };
    auto store_s = [&](int buf){
#pragma unroll
        for(int it=0; it<AV; it++){
            int u = tid + it*NTHREADS;
            int r = u/(BK/4), kq = u%(BK/4);
            As[buf][kq*4+0][r]=f2tf32(ra[it].x); As[buf][kq*4+1][r]=f2tf32(ra[it].y);
            As[buf][kq*4+2][r]=f2tf32(ra[it].z); As[buf][kq*4+3][r]=f2tf32(ra[it].w);
        }
#pragma unroll
        for(int it=0; it<BV; it++){
            int u = tid + it*NTHREADS;
            int kk = u/(BN/4), cq = u%(BN/4);
            Bs[buf][kk][cq*4+0]=f2tf32(rb[it].x); Bs[buf][kk][cq*4+1]=f2tf32(rb[it].y);
            Bs[buf][kk][cq*4+2]=f2tf32(rb[it].z); Bs[buf][kk][cq*4+3]=f2tf32(rb[it].w);
        }
    };

    load_g(0);
    store_s(0);
    __syncthreads();

    int T = K/BK;
    for(int kt=0; kt<T; kt++){
        if(kt+1 < T) load_g((kt+1)*BK);
        int buf = kt & 1;
#pragma unroll
        for(int ks=0; ks<BK/8; ks++){
            uint32_t af[MT][4], bf[NT2][2];
#pragma unroll
            for(int mt=0; mt<MT; mt++){
                int row = wm0 + mt*16 + g;
                af[mt][0] = As[buf][ks*8+tg  ][row];
                af[mt][1] = As[buf][ks*8+tg  ][row+8];
                af[mt][2] = As[buf][ks*8+tg+4][row];
                af[mt][3] = As[buf][ks*8+tg+4][row+8];
            }
#pragma unroll
            for(int nt=0; nt<NT2; nt++){
                int col = wn0 + nt*8 + g;
                bf[nt][0] = Bs[buf][ks*8+tg  ][col];
                bf[nt][1] = Bs[buf][ks*8+tg+4][col];
            }
#pragma unroll
            for(int mt=0; mt<MT; mt++)
#pragma unroll
                for(int nt=0; nt<NT2; nt++){
                    asm volatile(
                        "mma.sync.aligned.m16n8k8.row.col.f32.tf32.tf32.f32 "
                        "{%0,%1,%2,%3}, {%4,%5,%6,%7}, {%8,%9}, {%0,%1,%2,%3};"
                        : "+f"(acc[mt][nt][0]), "+f"(acc[mt][nt][1]),
                          "+f"(acc[mt][nt][2]), "+f"(acc[mt][nt][3])
                        : "r"(af[mt][0]), "r"(af[mt][1]), "r"(af[mt][2]), "r"(af[mt][3]),
                          "r"(bf[nt][0]), "r"(bf[nt][1]));
                }
        }
        if(kt+1 < T){
            store_s((kt+1)&1);
            __syncthreads();
        }
    }

    if(EPI == 3){
        float l0[MT], l1[MT];
#pragma unroll
        for(int mt=0; mt<MT; mt++){ l0[mt]=0.f; l1[mt]=0.f; }
#pragma unroll
        for(int mt=0; mt<MT; mt++){
            int rr0 = wm0 + mt*16 + g, rr1 = rr0 + 8;
            int s0 = sSrc[rr0], d0 = sDst[rr0];
            int s1 = sSrc[rr1], d1 = sDst[rr1];
#pragma unroll
            for(int nt=0; nt<NT2; nt++){
                int gc = n0 + wn0 + nt*8 + 2*tg;
                float a0 = lns[gc], a1 = lns[gc+1];
                float2 xs0 = *(const float2*)&aux1[(size_t)s0*ldx + gc];
                float2 xd0 = *(const float2*)&aux2[(size_t)d0*ldx + gc];
                float2 xs1 = *(const float2*)&aux1[(size_t)s1*ldx + gc];
                float2 xd1 = *(const float2*)&aux2[(size_t)d1*ldx + gc];
                float m00 = acc[mt][nt][0] + xs0.x + xd0.x; m00 = m00>0.f? m00 : 0.2f*m00;
                float m01 = acc[mt][nt][1] + xs0.y + xd0.y; m01 = m01>0.f? m01 : 0.2f*m01;
                float m10 = acc[mt][nt][2] + xs1.x + xd1.x; m10 = m10>0.f? m10 : 0.2f*m10;
                float m11 = acc[mt][nt][3] + xs1.y + xd1.y; m11 = m11>0.f? m11 : 0.2f*m11;
                l0[mt] += m00*a0 + m01*a1;
                l1[mt] += m10*a0 + m11*a1;
            }
        }
#pragma unroll
        for(int mt=0; mt<MT; mt++){
            l0[mt] += __shfl_xor_sync(0xffffffffu, l0[mt], 1);
            l0[mt] += __shfl_xor_sync(0xffffffffu, l0[mt], 2);
            l1[mt] += __shfl_xor_sync(0xffffffffu, l1[mt], 1);
            l1[mt] += __shfl_xor_sync(0xffffffffu, l1[mt], 2);
            if(tg == 0){
                int rr0 = wm0 + mt*16 + g;
                sEp[warp_n*BM + rr0]     = l0[mt];
                sEp[warp_n*BM + rr0 + 8] = l1[mt];
            }
        }
        __syncthreads();
        int row = tid & (BM-1), hh = tid >> 7;
        int grow = m0 + row;
        if(grow < M){
            float v = sEp[(2*hh)*BM + row] + sEp[(2*hh+1)*BM + row];
            C[(size_t)grow*4 + (n0>>6) + hh] = v;
        }
    } else if(EPI == 4){
        float sv[MT][NT2][4];
        float s1a[MT], s2a[MT], s1b[MT], s2b[MT];
#pragma unroll
        for(int mt=0; mt<MT; mt++){ s1a[mt]=s2a[mt]=s1b[mt]=s2b[mt]=0.f; }
#pragma unroll
        for(int mt=0; mt<MT; mt++){
            int rr0 = wm0 + mt*16 + g, rr1 = rr0 + 8;
            int s0 = sSrc[rr0], d0 = sDst[rr0];
            int s1i = sSrc[rr1], d1i = sDst[rr1];
#pragma unroll
            for(int nt=0; nt<NT2; nt++){
                int col = wn0 + nt*8 + 2*tg;
                float b0 = bias[col], b1 = bias[col+1];
                float2 p0 = *(const float2*)&aux1[(size_t)s0*ldx + col];
                float2 q0 = *(const float2*)&aux1[(size_t)d0*ldx + 64 + col];
                float2 p1 = *(const float2*)&aux1[(size_t)s1i*ldx + col];
                float2 q1 = *(const float2*)&aux1[(size_t)d1i*ldx + 64 + col];
                float v0 = siluf(acc[mt][nt][0]+b0+p0.x+q0.x);
                float v1 = siluf(acc[mt][nt][1]+b1+p0.y+q0.y);
                float v2 = siluf(acc[mt][nt][2]+b0+p1.x+q1.x);
                float v3 = siluf(acc[mt][nt][3]+b1+p1.y+q1.y);
                sv[mt][nt][0]=v0; sv[mt][nt][1]=v1; sv[mt][nt][2]=v2; sv[mt][nt][3]=v3;
                s1a[mt]+=v0+v1; s2a[mt]+=v0*v0+v1*v1;
                s1b[mt]+=v2+v3; s2b[mt]+=v2*v2+v3*v3;
            }
        }
#pragma unroll
        for(int mt=0; mt<MT; mt++){
#pragma unroll
            for(int o=1;o<4;o<<=1){
                s1a[mt] += __shfl_xor_sync(0xffffffffu, s1a[mt], o);
                s2a[mt] += __shfl_xor_sync(0xffffffffu, s2a[mt], o);
                s1b[mt] += __shfl_xor_sync(0xffffffffu, s1b[mt], o);
                s2b[mt] += __shfl_xor_sync(0xffffffffu, s2b[mt], o);
            }
            if(tg == 0){
                int r0 = wm0 + mt*16 + g;
                sEp[(warp_n*BM + r0)*2+0]   = s1a[mt];
                sEp[(warp_n*BM + r0)*2+1]   = s2a[mt];
                sEp[(warp_n*BM + r0+8)*2+0] = s1b[mt];
                sEp[(warp_n*BM + r0+8)*2+1] = s2b[mt];
            }
        }
        __syncthreads();
#pragma unroll
        for(int mt=0; mt<MT; mt++){
            int r0 = wm0 + mt*16 + g;
            float t1 = sEp[r0*2+0] + sEp[(BM+r0)*2+0];
            float t2 = sEp[r0*2+1] + sEp[(BM+r0)*2+1];
            float mu0 = t1*(1.f/BN);
            float iv0 = rsqrtf(t2*(1.f/BN)-mu0*mu0 + 1e-5f);
            int r1 = r0+8;
            float u1 = sEp[r1*2+0] + sEp[(BM+r1)*2+0];
            float u2 = sEp[r1*2+1] + sEp[(BM+r1)*2+1];
            float mu1 = u1*(1.f/BN);
            float iv1 = rsqrtf(u2*(1.f/BN)-mu1*mu1 + 1e-5f);
#pragma unroll
            for(int nt=0; nt<NT2; nt++){
                int col = wn0 + nt*8 + 2*tg;
                float g0 = lns[col], g1 = lns[col+1];
                float c0 = lnb[col], c1 = lnb[col+1];
                size_t ro0 = (size_t)(m0+r0)*ldc + col;
                size_t ro1 = (size_t)(m0+r1)*ldc + col;
                C[ro0]   = (sv[mt][nt][0]-mu0)*iv0*g0 + c0;
                C[ro0+1] = (sv[mt][nt][1]-mu0)*iv0*g1 + c1;
                C[ro1]   = (sv[mt][nt][2]-mu1)*iv1*g0 + c0;
                C[ro1+1] = (sv[mt][nt][3]-mu1)*iv1*g1 + c1;
            }
        }
    } else if(EPI == 5){
        float p0[MT], p1[MT];
#pragma unroll
        for(int mt=0; mt<MT; mt++){ p0[mt]=0.f; p1[mt]=0.f; }
#pragma unroll
        for(int mt=0; mt<MT; mt++){
#pragma unroll
            for(int nt=0; nt<NT2; nt++){
                int col = wn0 + nt*8 + 2*tg;
                float b0 = bias[col], b1 = bias[col+1];
                float w0 = lns[col],  w1 = lns[col+1];
                float v0 = siluf(acc[mt][nt][0]+b0);
                float v1 = siluf(acc[mt][nt][1]+b1);
                float v2 = siluf(acc[mt][nt][2]+b0);
                float v3 = siluf(acc[mt][nt][3]+b1);
                p0[mt] += v0*w0 + v1*w1;
                p1[mt] += v2*w0 + v3*w1;
            }
        }
#pragma unroll
        for(int mt=0; mt<MT; mt++){
            p0[mt] += __shfl_xor_sync(0xffffffffu, p0[mt], 1);
            p0[mt] += __shfl_xor_sync(0xffffffffu, p0[mt], 2);
            p1[mt] += __shfl_xor_sync(0xffffffffu, p1[mt], 1);
            p1[mt] += __shfl_xor_sync(0xffffffffu, p1[mt], 2);
            if(tg == 0){
                int rr0 = wm0 + mt*16 + g;
                sEp[warp_n*BM + rr0]     = p0[mt];
                sEp[warp_n*BM + rr0 + 8] = p1[mt];
            }
        }
        __syncthreads();
        if(tid < BM){
            int grow = m0 + tid;
            if(grow < M){
                float v = 0.f;
#pragma unroll
                for(int wn = 0; wn < WARPS_N; wn++) v += sEp[wn*BM + tid];
                g_gate[grow] = v + lnb[0];
            }
        }
    } else {
#pragma unroll
        for(int mt=0; mt<MT; mt++){
#pragma unroll
            for(int nt=0; nt<NT2; nt++){
                int col = n0 + wn0 + nt*8 + 2*tg;
                float b0 = bias? bias[col]   : 0.f;
                float b1 = bias? bias[col+1] : 0.f;
                int row0 = m0 + wm0 + mt*16 + g;
                if(row0 < M){
                    float v0 = acc[mt][nt][0] + b0;
                    float v1 = acc[mt][nt][1] + b1;
                    if(EPI==1){ v0 = siluf(v0); v1 = siluf(v1); }
                    C[(size_t)row0*ldc + col]   = v0;
                    C[(size_t)row0*ldc + col+1] = v1;
                }
                int row1 = row0 + 8;
                if(row1 < M){
                    float v2 = acc[mt][nt][2] + b0;
                    float v3 = acc[mt][nt][3] + b1;
                    if(EPI==1){ v2 = siluf(v2); v3 = siluf(v3); }
                    C[(size_t)row1*ldc + col]   = v2;
                    C[(size_t)row1*ldc + col+1] = v3;
                }
            }
        }
    }
}

// ---------------- per-node softmax + aggregation + bias + silu + LN(256) ----------------
__global__ void k_aggregate(const int* __restrict__ src,
                            const float* __restrict__ xl,
                            const float* __restrict__ bias,
                            const float* __restrict__ ln1s, const float* __restrict__ ln1b,
                            float* __restrict__ out)
{
    __shared__ float sm4[4], sinv[4];
    __shared__ int   sS[32];
    __shared__ float sA[32*4];
    __shared__ float red[16];

    int n = blockIdx.x, tid = threadIdx.x, lane = tid&31, warp = tid>>5;
    int b = g_rowptr[n];
    int cnt = g_rowptr[n+1] - b;

    if(warp == 0){
        float mx[4] = {-1e30f,-1e30f,-1e30f,-1e30f};
        for(int j=lane; j<cnt; j+=32){
            int eid = g_csr[b+j];
#pragma unroll
            for(int h=0;h<4;h++) mx[h] = fmaxf(mx[h], g_logits[eid*4+h]);
        }
#pragma unroll
        for(int h=0;h<4;h++)
            for(int o=16;o;o>>=1) mx[h] = fmaxf(mx[h], __shfl_xor_sync(0xffffffffu, mx[h], o));
        float su[4] = {0.f,0.f,0.f,0.f};
        for(int j=lane; j<cnt; j+=32){
            int eid = g_csr[b+j];
#pragma unroll
            for(int h=0;h<4;h++) su[h] += __expf(g_logits[eid*4+h] - mx[h]);
        }
#pragma unroll
        for(int h=0;h<4;h++)
            for(int o=16;o;o>>=1) su[h] += __shfl_xor_sync(0xffffffffu, su[h], o);
        if(lane < 4){ sm4[lane] = mx[lane]; sinv[lane] = 1.f/(su[lane] + 1e-16f); }
    }
    __syncthreads();

    float a0=0.f, a1=0.f, a2=0.f, a3=0.f;
    int c = tid, h = c>>6;
    for(int base=0; base<cnt; base+=32){
        int jn = min(32, cnt-base);
        if(tid < 32 && lane < jn){
            int eid = g_csr[b+base+lane];
            sS[lane] = (eid < Ee) ? src[eid] : n;
#pragma unroll
            for(int hh=0; hh<4; hh++)
                sA[lane*4+hh] = __expf(g_logits[eid*4+hh] - sm4[hh]) * sinv[hh];
        }
        __syncthreads();
        int j = 0;
        for(; j+4<=jn; j+=4){
            a0 += sA[(j+0)*4+h] * xl[(size_t)sS[j+0]*LDB + c];
            a1 += sA[(j+1)*4+h] * xl[(size_t)sS[j+1]*LDB + c];
            a2 += sA[(j+2)*4+h] * xl[(size_t)sS[j+2]*LDB + c];
            a3 += sA[(j+3)*4+h] * xl[(size_t)sS[j+3]*LDB + c];
        }
        for(; j<jn; j++)
            a0 += sA[j*4+h] * xl[(size_t)sS[j]*LDB + c];
        __syncthreads();
    }
    float acc = (a0+a1)+(a2+a3);

    float v = siluf(acc + bias[c]);
    float s1 = v, s2 = v*v;
    for(int o=16;o;o>>=1){ s1 += __shfl_xor_sync(0xffffffffu,s1,o); s2 += __shfl_xor_sync(0xffffffffu,s2,o); }
    if(lane == 0){ red[warp] = s1; red[8+warp] = s2; }
    __syncthreads();
    if(warp == 0){
        float a = (lane<8)? red[lane]   : 0.f;
        float q = (lane<8)? red[8+lane] : 0.f;
        for(int o=4;o;o>>=1){ a += __shfl_xor_sync(0xffffffffu,a,o); q += __shfl_xor_sync(0xffffffffu,q,o); }
        if(lane == 0){ red[0]=a; red[8]=q; }
    }
    __syncthreads();
    float mu  = red[0]*(1.f/256.f);
    float var = red[8]*(1.f/256.f) - mu*mu;
    out[(size_t)n*1024 + c] = (v-mu)*rsqrtf(var+1e-5f)*ln1s[c] + ln1b[c];
}

// ---------------- LN(256) on g_hfin ----------------
__global__ void k_ln256(const float* __restrict__ s, const float* __restrict__ b){
    __shared__ float red[16];
    int n = blockIdx.x, tid = threadIdx.x, lane = tid&31, warp = tid>>5;
    float v = g_hfin[(size_t)n*256+tid];
    float s1 = v, s2 = v*v;
    for(int o=16;o;o>>=1){ s1 += __shfl_xor_sync(0xffffffffu,s1,o); s2 += __shfl_xor_sync(0xffffffffu,s2,o); }
    if(lane==0){ red[warp]=s1; red[8+warp]=s2; }
    __syncthreads();
    if(warp==0){
        float a = (lane<8)? red[lane]:0.f;
        float q = (lane<8)? red[8+lane]:0.f;
        for(int o=4;o;o>>=1){ a += __shfl_xor_sync(0xffffffffu,a,o); q += __shfl_xor_sync(0xffffffffu,q,o); }
        if(lane==0){ red[0]=a; red[8]=q; }
    }
    __syncthreads();
    float mu = red[0]*(1.f/256.f);
    float var = red[8]*(1.f/256.f)-mu*mu;
    g_hfin[(size_t)n*256+tid] = (v-mu)*rsqrtf(var+1e-5f)*s[tid]+b[tid];
}

// ---------------- per-graph pooling + head ----------------
__global__ void k_pool(const int* __restrict__ batch, const float* __restrict__ hW,
                       const float* __restrict__ hb, float* __restrict__ out){
    __shared__ int bnd[2];
    __shared__ float red[8];
    __shared__ float sstat[2];
    int g = blockIdx.x, tid = threadIdx.x, lane = tid&31, warp = tid>>5;
    if(tid < 2){
        int tgt = g + tid;
        int lo=0, hi=Nn;
        while(lo<hi){ int m=(lo+hi)>>1; if(batch[m]<tgt) lo=m+1; else hi=m; }
        bnd[tid]=lo;
    }
    __syncthreads();
    int lo=bnd[0], hi=bnd[1];

    float m = -1e30f;
    for(int i=lo+tid;i<hi;i+=256) m = fmaxf(m, g_gate[i]);
    for(int o=16;o;o>>=1) m = fmaxf(m, __shfl_xor_sync(0xffffffffu,m,o));
    if(lane==0) red[warp]=m;
    __syncthreads();
    if(tid==0){
        float v=red[0];
        for(int w2=1;w2<8;w2++) v = fmaxf(v, red[w2]);
        if(v < -1e29f) v = 0.f;
        sstat[0]=v;
    }
    __syncthreads();
    m = sstat[0];
    float sd = 0.f;
    for(int i=lo+tid;i<hi;i+=256) sd += __expf(g_gate[i]-m);
    for(int o=16;o;o>>=1) sd += __shfl_xor_sync(0xffffffffu,sd,o);
    if(lane==0) red[warp]=sd;
    __syncthreads();
    if(tid==0){
        float v=0.f;
        for(int w2=0;w2<8;w2++) v += red[w2];
        sstat[1] = 1.f/(v+1e-16f);
    }
    __syncthreads();
    float inv = sstat[1];
    float acc = 0.f;
    for(int i=lo;i<hi;i++){
        float w2 = __expf(g_gate[i]-m)*inv;
        acc += w2 * g_hfin[(size_t)i*256+tid];
    }
    float pv = acc*hW[tid];
    for(int o=16;o;o>>=1) pv += __shfl_xor_sync(0xffffffffu,pv,o);
    if(lane==0) red[warp]=pv;
    __syncthreads();
    if(tid==0){
        float v=0.f;
        for(int w2=0;w2<8;w2++) v += red[w2];
        out[g] = v + hb[0];
    }
}

// ---------------- host ----------------
extern "C" void kernel_launch(void* const* d_in, const int* in_sizes, int n_in,
                              void* d_out, int out_size){
    const float* x     = (const float*)d_in[0];
    const int*   ei    = (const int*)  d_in[1];
    const float* eattr = (const float*)d_in[2];
    const int*   batch = (const int*)  d_in[3];
    const float* atomW = (const float*)d_in[4];
    const float* atomB = (const float*)d_in[5];
    const float* bondW = (const float*)d_in[6];
    const float* bondB = (const float*)d_in[7];
    const float* Wl    = (const float*)d_in[8];
    const float* bl    = (const float*)d_in[9];
    const float* Wr    = (const float*)d_in[10];
    const float* br    = (const float*)d_in[11];
    const float* We    = (const float*)d_in[12];
    const float* att   = (const float*)d_in[13];
    const float* bias  = (const float*)d_in[14];
    const float* ln1s  = (const float*)d_in[15];
    const float* ln1b  = (const float*)d_in[16];
    const float* eW    = (const float*)d_in[17];
    const float* eb    = (const float*)d_in[18];
    const float* ln2s  = (const float*)d_in[19];
    const float* ln2b  = (const float*)d_in[20];
    const float* jkW   = (const float*)d_in[21];
    const float* jkb   = (const float*)d_in[22];
    const float* ln3s  = (const float*)d_in[23];
    const float* ln3b  = (const float*)d_in[24];
    const float* gW1   = (const float*)d_in[25];
    const float* gb1   = (const float*)d_in[26];
    const float* gW2   = (const float*)d_in[27];
    const float* gb2   = (const float*)d_in[28];
    const float* hW    = (const float*)d_in[29];
    const float* hb    = (const float*)d_in[30];
    float* out = (float*)d_out;

    const int* src = ei;
    const int* dst = ei + Ee;

    float *h0p, *eAp, *eBp, *bigp, *pqp, *hjkp, *hfinp, *logp, *wpk, *bpk, *wpq;
    int *srcxp, *dstxp;
    cudaGetSymbolAddress((void**)&h0p,   g_h0);
    cudaGetSymbolAddress((void**)&eAp,   g_eA);
    cudaGetSymbolAddress((void**)&eBp,   g_eB);
    cudaGetSymbolAddress((void**)&bigp,  g_big);
    cudaGetSymbolAddress((void**)&pqp,   g_pq);
    cudaGetSymbolAddress((void**)&hjkp,  g_hjk);
    cudaGetSymbolAddress((void**)&hfinp, g_hfin);
    cudaGetSymbolAddress((void**)&logp,  g_logits);
    cudaGetSymbolAddress((void**)&wpk,   g_wpack);
    cudaGetSymbolAddress((void**)&bpk,   g_bpack);
    cudaGetSymbolAddress((void**)&wpq,   g_wpq);
    cudaGetSymbolAddress((void**)&srcxp, g_srcx);
    cudaGetSymbolAddress((void**)&dstxp, g_dstx);

    static cudaStream_t s2 = nullptr;
    static cudaEvent_t evFork, evP, evCSR, evL[4], evA[3];
    if(!s2){
        cudaStreamCreateWithFlags(&s2, cudaStreamNonBlocking);
        cudaEventCreateWithFlags(&evFork, cudaEventDisableTiming);
        cudaEventCreateWithFlags(&evP,    cudaEventDisableTiming);
        cudaEventCreateWithFlags(&evCSR,  cudaEventDisableTiming);
        for(int i=0;i<4;i++) cudaEventCreateWithFlags(&evL[i], cudaEventDisableTiming);
        for(int i=0;i<3;i++) cudaEventCreateWithFlags(&evA[i], cudaEventDisableTiming);
    }

    // ---- fork s2 off the main (captured) stream ----
    cudaEventRecord(evFork, 0);
    cudaStreamWaitEvent(s2, evFork, 0);

    // s2: encoders + weight packing + extidx
    k_atom_enc<<<(Nn*Dd+255)/256,256,0,s2>>>(x, atomW, atomB);
    k_bond_enc<<<(Ee*EDd+255)/256,256,0,s2>>>(eattr, bondW, bondB);
    k_pack<<<(4*Dd*LDB+255)/256,256,0,s2>>>(Wl, Wr);
    k_packpq<<<(4*Dd*128+255)/256,256,0,s2>>>(eW);
    k_packb<<<(4*LDB+255)/256,256,0,s2>>>(bl, br);
    k_extidx<<<(ENt+255)/256,256,0,s2>>>(src, dst);
    cudaEventRecord(evP, s2);

    // s1: CSR build (multi-block scan)
    k_zero_deg<<<(Nn+255)/256,256>>>();
    k_deg <<<(Ee+255)/256,256>>>(dst);
    k_scan_local<<<20,1024>>>();
    k_scan_off<<<1,32>>>();
    k_scan_add<<<(Nn+255)/256,256>>>();
    k_fill<<<(Ee+255)/256,256>>>(dst);
    k_selfloop<<<(Nn+255)/256,256>>>();
    cudaEventRecord(evCSR, 0);

    // s2: loope(0)
    cudaStreamWaitEvent(s2, evCSR, 0);
    k_loope<<<Nn,64,0,s2>>>(eAp);
    cudaEventRecord(evL[0], s2);

    cudaStreamWaitEvent(0, evP, 0);

    for(int l=0; l<4; l++){
        float* e_cur  = (l&1) ? eBp : eAp;
        float* e_next = (l&1) ? eAp : eBp;
        const float* hcur = (l==0) ? h0p : (hjkp + (l-1)*256);
        int ldh = (l==0) ? 256 : 1024;

        // s1: packed node GEMM [xl|xr] = hcur @ [Wl|Wr]
        dim3 gN(LDB/128, (Nn+127)/128);
        mma_gemm<128,128,16,64,32,0,0><<<gN,256>>>(
            hcur, ldh, wpk + l*Dd*LDB, LDB, bpk + l*LDB, bigp, LDB, Nn, 256,
            nullptr,nullptr,nullptr,nullptr, nullptr,nullptr, 0);

        cudaStreamWaitEvent(0, evL[l], 0);

        // s1: logits (double-buffered BK=16 — proven fastest)
        dim3 gL(2,(ENt+127)/128);
        mma_gemm<128,128,16,64,32,1,3><<<gL,256>>>(
            e_cur, 64, We + l*EDd*Dd, 256, nullptr, logp, 4, ENt, 64,
            bigp, bigp + 256, srcxp, dstxp, att + l*256, nullptr, LDB);

        // s1: aggregate
        k_aggregate<<<Nn,256>>>(src, bigp, bias + l*256, ln1s + l*256, ln1b + l*256,
                                hjkp + l*256);

        if(l < 3){
            cudaEventRecord(evA[l], 0);
            // s2: edge path
            cudaStreamWaitEvent(s2, evA[l], 0);
            dim3 gPQ(1,(Nn+127)/128);
            mma_gemm<128,128,16,64,32,0,0><<<gPQ,256,0,s2>>>(
                hjkp + l*256, 1024, wpq + l*Dd*128, 128, nullptr, pqp, 128, Nn, 256,
                nullptr,nullptr,nullptr,nullptr, nullptr,nullptr, 0);
            dim3 gE(1, Ee/128);
            mma_gemm<128,64,16,32,32,0,4><<<gE,256,0,s2>>>(
                e_cur, 64, eW + l*576*64 + 512*64, 64, eb + l*64, e_next, 64, Ee, 64,
                pqp, nullptr, src, dst, ln2s + l*64, ln2b + l*64, 128);
            k_loope<<<Nn,64,0,s2>>>(e_next);
            cudaEventRecord(evL[l+1], s2);
        }
    }

    // tail on s1
    dim3 gJK(2,(Nn+127)/128);
    mma_gemm<128,128,16,64,32,0,1><<<gJK,256>>>(
        hjkp, 1024, jkW, 256, jkb, hfinp, 256, Nn, 1024,
        nullptr,nullptr,nullptr,nullptr, nullptr,nullptr, 0);
    k_ln256<<<Nn,256>>>(ln3s, ln3b);

    dim3 gG1(1,(Nn+127)/128);
    mma_gemm<128,128,16,64,32,0,5><<<gG1,256>>>(
        hfinp, 256, gW1, 128, gb1, nullptr, 0, Nn, 256,
        nullptr,nullptr,nullptr,nullptr, gW2, gb2, 0);

    k_pool<<<Gg,256>>>(batch, hW, hb, out);
}

// round 15
// speedup vs baseline: 1.1099x; 1.0005x over previous
#include <cuda_runtime.h>
#include <math.h>
#include <stdint.h>

#define Nn 20000
#define Ee 320000
#define ENt 340000
#define Gg 128
#define Dd 256
#define EDd 64
#define LDB 512

// ---------------- static scratch ----------------
__device__ float g_h0[Nn*Dd];
__device__ float g_eA[Ee*EDd];
__device__ float g_eB[Ee*EDd];
__device__ float g_loope[Nn*EDd];
__device__ float g_big[Nn*LDB];          // [xl | xr] stride 512
__device__ float g_pq[Nn*128];           // [P | Q] stride 128
__device__ float g_logits[ENt*4];
__device__ float g_hjk[Nn*Dd*4];
__device__ float g_hfin[Nn*Dd];
__device__ float g_gate[Nn];
__device__ float g_wpack[4*Dd*LDB];
__device__ float g_bpack[4*LDB];
__device__ float g_wpq[4*Dd*128];
__device__ int   g_deg[Nn];
__device__ int   g_rowptr[Nn+1];
__device__ int   g_fill[Nn];
__device__ int   g_csr[ENt];
__device__ int   g_srcx[ENt];
__device__ int   g_dstx[ENt];
__device__ int   g_bsum[20];

__device__ __forceinline__ float siluf(float v){ return v/(1.f+__expf(-v)); }

__device__ __forceinline__ uint32_t f2tf32(float f){
    uint32_t r;
    asm("cvt.rna.tf32.f32 %0, %1;" : "=r"(r) : "f"(f));
    return r;
}

// ---------------- init / encoders / packing ----------------
__global__ void k_zero_deg(){
    int i = blockIdx.x*blockDim.x + threadIdx.x;
    if(i < Nn) g_deg[i] = 0;
}

__global__ void k_atom_enc(const float* __restrict__ x, const float* __restrict__ W,
                           const float* __restrict__ b){
    int idx = blockIdx.x*blockDim.x + threadIdx.x;
    if(idx >= Nn*Dd) return;
    int n = idx >> 8, c = idx & 255;
    float acc = b[c];
#pragma unroll
    for(int k=0;k<9;k++) acc += x[n*9+k]*W[k*Dd+c];
    g_h0[idx] = acc;
}

__global__ void k_bond_enc(const float* __restrict__ ea, const float* __restrict__ W,
                           const float* __restrict__ b){
    int idx = blockIdx.x*blockDim.x + threadIdx.x;
    if(idx >= Ee*EDd) return;
    int e = idx >> 6, c = idx & 63;
    float acc = b[c];
#pragma unroll
    for(int k=0;k<3;k++) acc += ea[e*3+k]*W[k*EDd+c];
    g_eA[idx] = acc;
}

__global__ void k_pack(const float* __restrict__ Wl, const float* __restrict__ Wr){
    int idx = blockIdx.x*blockDim.x + threadIdx.x;
    if(idx >= 4*Dd*LDB) return;
    int l = idx/(Dd*LDB);
    int r = (idx/LDB)%Dd;
    int n = idx%LDB;
    g_wpack[idx] = (n < 256) ? Wl[l*65536 + r*256 + n] : Wr[l*65536 + r*256 + (n-256)];
}

__global__ void k_packpq(const float* __restrict__ eW){
    int idx = blockIdx.x*blockDim.x + threadIdx.x;
    if(idx >= 4*Dd*128) return;
    int l = idx/(Dd*128);
    int r = (idx/128)%Dd;
    int n = idx%128;
    g_wpq[idx] = (n < 64) ? eW[l*36864 + r*64 + n] : eW[l*36864 + (256+r)*64 + (n-64)];
}

__global__ void k_packb(const float* __restrict__ bl, const float* __restrict__ br){
    int idx = blockIdx.x*blockDim.x + threadIdx.x;
    if(idx >= 4*LDB) return;
    int l = idx/LDB, n = idx%LDB;
    g_bpack[idx] = (n<256) ? bl[l*256+n] : br[l*256+(n-256)];
}

__global__ void k_extidx(const int* __restrict__ src, const int* __restrict__ dst){
    int i = blockIdx.x*blockDim.x + threadIdx.x;
    if(i >= ENt) return;
    if(i < Ee){ g_srcx[i] = src[i]; g_dstx[i] = dst[i]; }
    else      { g_srcx[i] = g_dstx[i] = i - Ee; }
}

// ---------------- CSR by dst (multi-block scan) ----------------
__global__ void k_deg(const int* __restrict__ dst){
    int e = blockIdx.x*blockDim.x + threadIdx.x;
    if(e < Ee) atomicAdd(&g_deg[dst[e]], 1);
}

__global__ void k_scan_local(){
    __shared__ int sd[1024];
    int b = blockIdx.x, tid = threadIdx.x;
    int i = b*1024 + tid;
    int v = (i < Nn) ? (g_deg[i] + 1) : 0;
    sd[tid] = v; __syncthreads();
    for(int off=1; off<1024; off<<=1){
        int t = (tid >= off) ? sd[tid-off] : 0;
        __syncthreads();
        sd[tid] += t; __syncthreads();
    }
    if(i < Nn) g_rowptr[i+1] = sd[tid];
    if(tid == 1023) g_bsum[b] = sd[1023];
}

__global__ void k_scan_off(){
    if(threadIdx.x == 0){
        int acc = 0;
        for(int b=0;b<20;b++){ int t = g_bsum[b]; g_bsum[b] = acc; acc += t; }
        g_rowptr[0] = 0;
    }
}

__global__ void k_scan_add(){
    int i = blockIdx.x*blockDim.x + threadIdx.x;
    if(i < Nn){
        int r = g_rowptr[i+1] + g_bsum[i>>10];
        g_rowptr[i+1] = r;
        g_fill[i] = r - (g_deg[i] + 1);
    }
}

__global__ void k_fill(const int* __restrict__ dst){
    int e = blockIdx.x*blockDim.x + threadIdx.x;
    if(e < Ee){ int p = atomicAdd(&g_fill[dst[e]], 1); g_csr[p] = e; }
}

__global__ void k_selfloop(){
    int n = blockIdx.x*blockDim.x + threadIdx.x;
    if(n < Nn) g_csr[g_rowptr[n+1]-1] = Ee + n;
}

__global__ void k_loope(const float* __restrict__ e){
    int n = blockIdx.x;
    int tid = threadIdx.x;           // 64 threads
    int b = g_rowptr[n];
    int cnt = g_rowptr[n+1] - 1 - b;
    float acc = 0.f;
    for(int j=0;j<cnt;j++){
        int eid = g_csr[b+j];
        acc += e[(size_t)eid*EDd + tid];
    }
    g_loope[n*EDd + tid] = acc / (float)max(cnt, 1);
}

// ---------------- tf32 tensor-core GEMM, double-buffered ----------------
// GMODE: 0 = plain A; 1 = rows < Ee from A, rows >= Ee from g_loope
// EPI: 0 = +bias; 1 = +bias+silu
//      3 = GATv2 logits epilogue -> C=[M,4]
//      4 = edge MLP epilogue (silu+LN64)
//      5 = gate epilogue -> g_gate[row]
//      7 = +bias+silu+LayerNorm(BN) fused (full-row blocks, row-guarded)
template<int BM,int BN,int BK,int WM,int WN,int GMODE,int EPI>
__global__ void mma_gemm(const float* __restrict__ A, int lda,
                         const float* __restrict__ B, int ldb,
                         const float* __restrict__ bias,
                         float* __restrict__ C, int ldc,
                         int M, int K,
                         const float* __restrict__ aux1,
                         const float* __restrict__ aux2,
                         const int* __restrict__ srcv, const int* __restrict__ dstv,
                         const float* __restrict__ lns, const float* __restrict__ lnb,
                         int ldx)
{
    constexpr int WARPS_N = BN/WN, WARPS_M = BM/WM;
    constexpr int NTHREADS = WARPS_M*WARPS_N*32;
    constexpr int MT = WM/16, NT2 = WN/8;
    constexpr int PAD = 8;
    __shared__ uint32_t As[2][BK][BM+PAD];
    __shared__ uint32_t Bs[2][BK][BN+PAD];
    __shared__ int sSrc[(EPI==3||EPI==4)?BM:1];
    __shared__ int sDst[(EPI==3||EPI==4)?BM:1];
    __shared__ float sEp[(EPI==7)?2*WARPS_N*BM : ((EPI>=3)?4*BM:1)];

    int tid = threadIdx.x;
    int m0 = blockIdx.y*BM, n0 = blockIdx.x*BN;

    if(EPI == 3 || EPI == 4){
        for(int t=tid; t<BM; t+=NTHREADS){
            int r = m0 + t;
            sSrc[t] = (r < M) ? srcv[r] : 0;
            sDst[t] = (r < M) ? dstv[r] : 0;
        }
        __syncthreads();
    }

    int warp = tid>>5, lane = tid&31;
    int warp_n = warp % WARPS_N, warp_m = warp / WARPS_N;
    int wm0 = warp_m*WM, wn0 = warp_n*WN;
    int g = lane>>2, tg = lane&3;

    float acc[MT][NT2][4];
#pragma unroll
    for(int i=0;i<MT;i++)
#pragma unroll
        for(int j=0;j<NT2;j++)
#pragma unroll
            for(int q=0;q<4;q++) acc[i][j][q] = 0.f;

    constexpr int AV = (BM*BK/4)/NTHREADS;
    constexpr int BV = (BK*BN/4)/NTHREADS;
    float4 ra[AV], rb[BV];

    auto load_g = [&](int k0){
#pragma unroll
        for(int it=0; it<AV; it++){
            int u = tid + it*NTHREADS;
            int r = u/(BK/4), kq = u%(BK/4);
            int k = k0 + kq*4;
            int grow = m0 + r;
            float4 v;
            if(GMODE == 1){
                if(grow < Ee)       v = *(const float4*)(A + (size_t)grow*64 + k);
                else if(grow < M)   v = *(const float4*)(g_loope + (size_t)(grow-Ee)*64 + k);
                else                v = make_float4(0.f,0.f,0.f,0.f);
            } else {
                if(grow < M) v = *(const float4*)(A + (size_t)grow*lda + k);
                else         v = make_float4(0.f,0.f,0.f,0.f);
            }
            ra[it] = v;
        }
#pragma unroll
        for(int it=0; it<BV; it++){
            int u = tid + it*NTHREADS;
            int kk = u/(BN/4), cq = u%(BN/4);
            rb[it] = *(const float4*)(B + (size_t)(k0+kk)*ldb + n0 + cq*4);
        }
    };
    auto store_s = [&](int buf){
#pragma unroll
        for(int it=0; it<AV; it++){
            int u = tid + it*NTHREADS;
            int r = u/(BK/4), kq = u%(BK/4);
            As[buf][kq*4+0][r]=f2tf32(ra[it].x); As[buf][kq*4+1][r]=f2tf32(ra[it].y);
            As[buf][kq*4+2][r]=f2tf32(ra[it].z); As[buf][kq*4+3][r]=f2tf32(ra[it].w);
        }
#pragma unroll
        for(int it=0; it<BV; it++){
            int u = tid + it*NTHREADS;
            int kk = u/(BN/4), cq = u%(BN/4);
            Bs[buf][kk][cq*4+0]=f2tf32(rb[it].x); Bs[buf][kk][cq*4+1]=f2tf32(rb[it].y);
            Bs[buf][kk][cq*4+2]=f2tf32(rb[it].z); Bs[buf][kk][cq*4+3]=f2tf32(rb[it].w);
        }
    };

    load_g(0);
    store_s(0);
    __syncthreads();

    int T = K/BK;
    for(int kt=0; kt<T; kt++){
        if(kt+1 < T) load_g((kt+1)*BK);
        int buf = kt & 1;
#pragma unroll
        for(int ks=0; ks<BK/8; ks++){
            uint32_t af[MT][4], bf[NT2][2];
#pragma unroll
            for(int mt=0; mt<MT; mt++){
                int row = wm0 + mt*16 + g;
                af[mt][0] = As[buf][ks*8+tg  ][row];
                af[mt][1] = As[buf][ks*8+tg  ][row+8];
                af[mt][2] = As[buf][ks*8+tg+4][row];
                af[mt][3] = As[buf][ks*8+tg+4][row+8];
            }
#pragma unroll
            for(int nt=0; nt<NT2; nt++){
                int col = wn0 + nt*8 + g;
                bf[nt][0] = Bs[buf][ks*8+tg  ][col];
                bf[nt][1] = Bs[buf][ks*8+tg+4][col];
            }
#pragma unroll
            for(int mt=0; mt<MT; mt++)
#pragma unroll
                for(int nt=0; nt<NT2; nt++){
                    asm volatile(
                        "mma.sync.aligned.m16n8k8.row.col.f32.tf32.tf32.f32 "
                        "{%0,%1,%2,%3}, {%4,%5,%6,%7}, {%8,%9}, {%0,%1,%2,%3};"
                        : "+f"(acc[mt][nt][0]), "+f"(acc[mt][nt][1]),
                          "+f"(acc[mt][nt][2]), "+f"(acc[mt][nt][3])
                        : "r"(af[mt][0]), "r"(af[mt][1]), "r"(af[mt][2]), "r"(af[mt][3]),
                          "r"(bf[nt][0]), "r"(bf[nt][1]));
                }
        }
        if(kt+1 < T){
            store_s((kt+1)&1);
            __syncthreads();
        }
    }

    if(EPI == 3){
        float l0[MT], l1[MT];
#pragma unroll
        for(int mt=0; mt<MT; mt++){ l0[mt]=0.f; l1[mt]=0.f; }
#pragma unroll
        for(int mt=0; mt<MT; mt++){
            int rr0 = wm0 + mt*16 + g, rr1 = rr0 + 8;
            int s0 = sSrc[rr0], d0 = sDst[rr0];
            int s1 = sSrc[rr1], d1 = sDst[rr1];
#pragma unroll
            for(int nt=0; nt<NT2; nt++){
                int gc = n0 + wn0 + nt*8 + 2*tg;
                float a0 = lns[gc], a1 = lns[gc+1];
                float2 xs0 = *(const float2*)&aux1[(size_t)s0*ldx + gc];
                float2 xd0 = *(const float2*)&aux2[(size_t)d0*ldx + gc];
                float2 xs1 = *(const float2*)&aux1[(size_t)s1*ldx + gc];
                float2 xd1 = *(const float2*)&aux2[(size_t)d1*ldx + gc];
                float m00 = acc[mt][nt][0] + xs0.x + xd0.x; m00 = m00>0.f? m00 : 0.2f*m00;
                float m01 = acc[mt][nt][1] + xs0.y + xd0.y; m01 = m01>0.f? m01 : 0.2f*m01;
                float m10 = acc[mt][nt][2] + xs1.x + xd1.x; m10 = m10>0.f? m10 : 0.2f*m10;
                float m11 = acc[mt][nt][3] + xs1.y + xd1.y; m11 = m11>0.f? m11 : 0.2f*m11;
                l0[mt] += m00*a0 + m01*a1;
                l1[mt] += m10*a0 + m11*a1;
            }
        }
#pragma unroll
        for(int mt=0; mt<MT; mt++){
            l0[mt] += __shfl_xor_sync(0xffffffffu, l0[mt], 1);
            l0[mt] += __shfl_xor_sync(0xffffffffu, l0[mt], 2);
            l1[mt] += __shfl_xor_sync(0xffffffffu, l1[mt], 1);
            l1[mt] += __shfl_xor_sync(0xffffffffu, l1[mt], 2);
            if(tg == 0){
                int rr0 = wm0 + mt*16 + g;
                sEp[warp_n*BM + rr0]     = l0[mt];
                sEp[warp_n*BM + rr0 + 8] = l1[mt];
            }
        }
        __syncthreads();
        int row = tid & (BM-1), hh = tid >> 7;
        int grow = m0 + row;
        if(grow < M){
            float v = sEp[(2*hh)*BM + row] + sEp[(2*hh+1)*BM + row];
            C[(size_t)grow*4 + (n0>>6) + hh] = v;
        }
    } else if(EPI == 4){
        float sv[MT][NT2][4];
        float s1a[MT], s2a[MT], s1b[MT], s2b[MT];
#pragma unroll
        for(int mt=0; mt<MT; mt++){ s1a[mt]=s2a[mt]=s1b[mt]=s2b[mt]=0.f; }
#pragma unroll
        for(int mt=0; mt<MT; mt++){
            int rr0 = wm0 + mt*16 + g, rr1 = rr0 + 8;
            int s0 = sSrc[rr0], d0 = sDst[rr0];
            int s1i = sSrc[rr1], d1i = sDst[rr1];
#pragma unroll
            for(int nt=0; nt<NT2; nt++){
                int col = wn0 + nt*8 + 2*tg;
                float b0 = bias[col], b1 = bias[col+1];
                float2 p0 = *(const float2*)&aux1[(size_t)s0*ldx + col];
                float2 q0 = *(const float2*)&aux1[(size_t)d0*ldx + 64 + col];
                float2 p1 = *(const float2*)&aux1[(size_t)s1i*ldx + col];
                float2 q1 = *(const float2*)&aux1[(size_t)d1i*ldx + 64 + col];
                float v0 = siluf(acc[mt][nt][0]+b0+p0.x+q0.x);
                float v1 = siluf(acc[mt][nt][1]+b1+p0.y+q0.y);
                float v2 = siluf(acc[mt][nt][2]+b0+p1.x+q1.x);
                float v3 = siluf(acc[mt][nt][3]+b1+p1.y+q1.y);
                sv[mt][nt][0]=v0; sv[mt][nt][1]=v1; sv[mt][nt][2]=v2; sv[mt][nt][3]=v3;
                s1a[mt]+=v0+v1; s2a[mt]+=v0*v0+v1*v1;
                s1b[mt]+=v2+v3; s2b[mt]+=v2*v2+v3*v3;
            }
        }
#pragma unroll
        for(int mt=0; mt<MT; mt++){
#pragma unroll
            for(int o=1;o<4;o<<=1){
                s1a[mt] += __shfl_xor_sync(0xffffffffu, s1a[mt], o);
                s2a[mt] += __shfl_xor_sync(0xffffffffu, s2a[mt], o);
                s1b[mt] += __shfl_xor_sync(0xffffffffu, s1b[mt], o);
                s2b[mt] += __shfl_xor_sync(0xffffffffu, s2b[mt], o);
            }
            if(tg == 0){
                int r0 = wm0 + mt*16 + g;
                sEp[(warp_n*BM + r0)*2+0]   = s1a[mt];
                sEp[(warp_n*BM + r0)*2+1]   = s2a[mt];
                sEp[(warp_n*BM + r0+8)*2+0] = s1b[mt];
                sEp[(warp_n*BM + r0+8)*2+1] = s2b[mt];
            }
        }
        __syncthreads();
#pragma unroll
        for(int mt=0; mt<MT; mt++){
            int r0 = wm0 + mt*16 + g;
            float t1 = sEp[r0*2+0] + sEp[(BM+r0)*2+0];
            float t2 = sEp[r0*2+1] + sEp[(BM+r0)*2+1];
            float mu0 = t1*(1.f/BN);
            float iv0 = rsqrtf(t2*(1.f/BN)-mu0*mu0 + 1e-5f);
            int r1 = r0+8;
            float u1 = sEp[r1*2+0] + sEp[(BM+r1)*2+0];
            float u2 = sEp[r1*2+1] + sEp[(BM+r1)*2+1];
            float mu1 = u1*(1.f/BN);
            float iv1 = rsqrtf(u2*(1.f/BN)-mu1*mu1 + 1e-5f);
#pragma unroll
            for(int nt=0; nt<NT2; nt++){
                int col = wn0 + nt*8 + 2*tg;
                float g0 = lns[col], g1 = lns[col+1];
                float c0 = lnb[col], c1 = lnb[col+1];
                size_t ro0 = (size_t)(m0+r0)*ldc + col;
                size_t ro1 = (size_t)(m0+r1)*ldc + col;
                C[ro0]   = (sv[mt][nt][0]-mu0)*iv0*g0 + c0;
                C[ro0+1] = (sv[mt][nt][1]-mu0)*iv0*g1 + c1;
                C[ro1]   = (sv[mt][nt][2]-mu1)*iv1*g0 + c0;
                C[ro1+1] = (sv[mt][nt][3]-mu1)*iv1*g1 + c1;
            }
        }
    } else if(EPI == 7){
        // bias + silu + LayerNorm(BN) with full row per block (WARPS_N partial sums)
        float sv[MT][NT2][4];
        float s1a[MT], s2a[MT], s1b[MT], s2b[MT];
#pragma unroll
        for(int mt=0; mt<MT; mt++){ s1a[mt]=s2a[mt]=s1b[mt]=s2b[mt]=0.f; }
#pragma unroll
        for(int mt=0; mt<MT; mt++){
#pragma unroll
            for(int nt=0; nt<NT2; nt++){
                int col = wn0 + nt*8 + 2*tg;
                float b0 = bias[col], b1 = bias[col+1];
                float v0 = siluf(acc[mt][nt][0]+b0);
                float v1 = siluf(acc[mt][nt][1]+b1);
                float v2 = siluf(acc[mt][nt][2]+b0);
                float v3 = siluf(acc[mt][nt][3]+b1);
                sv[mt][nt][0]=v0; sv[mt][nt][1]=v1; sv[mt][nt][2]=v2; sv[mt][nt][3]=v3;
                s1a[mt]+=v0+v1; s2a[mt]+=v0*v0+v1*v1;
                s1b[mt]+=v2+v3; s2b[mt]+=v2*v2+v3*v3;
            }
        }
#pragma unroll
        for(int mt=0; mt<MT; mt++){
#pragma unroll
            for(int o=1;o<4;o<<=1){
                s1a[mt] += __shfl_xor_sync(0xffffffffu, s1a[mt], o);
                s2a[mt] += __shfl_xor_sync(0xffffffffu, s2a[mt], o);
                s1b[mt] += __shfl_xor_sync(0xffffffffu, s1b[mt], o);
                s2b[mt] += __shfl_xor_sync(0xffffffffu, s2b[mt], o);
            }
            if(tg == 0){
                int r0 = wm0 + mt*16 + g;
                sEp[(warp_n*BM + r0)*2+0]   = s1a[mt];
                sEp[(warp_n*BM + r0)*2+1]   = s2a[mt];
                sEp[(warp_n*BM + r0+8)*2+0] = s1b[mt];
                sEp[(warp_n*BM + r0+8)*2+1] = s2b[mt];
            }
        }
        __syncthreads();
#pragma unroll
        for(int mt=0; mt<MT; mt++){
            int r0 = wm0 + mt*16 + g;
            int r1 = r0+8;
            float t1=0.f,t2=0.f,u1=0.f,u2=0.f;
#pragma unroll
            for(int wn=0; wn<WARPS_N; wn++){
                t1 += sEp[(wn*BM + r0)*2+0];
                t2 += sEp[(wn*BM + r0)*2+1];
                u1 += sEp[(wn*BM + r1)*2+0];
                u2 += sEp[(wn*BM + r1)*2+1];
            }
            float mu0 = t1*(1.f/BN);
            float iv0 = rsqrtf(t2*(1.f/BN)-mu0*mu0 + 1e-5f);
            float mu1 = u1*(1.f/BN);
            float iv1 = rsqrtf(u2*(1.f/BN)-mu1*mu1 + 1e-5f);
            bool ok0 = (m0+r0) < M, ok1 = (m0+r1) < M;
#pragma unroll
            for(int nt=0; nt<NT2; nt++){
                int col = wn0 + nt*8 + 2*tg;
                float g0 = lns[col], g1 = lns[col+1];
                float c0 = lnb[col], c1 = lnb[col+1];
                if(ok0){
                    size_t ro0 = (size_t)(m0+r0)*ldc + col;
                    C[ro0]   = (sv[mt][nt][0]-mu0)*iv0*g0 + c0;
                    C[ro0+1] = (sv[mt][nt][1]-mu0)*iv0*g1 + c1;
                }
                if(ok1){
                    size_t ro1 = (size_t)(m0+r1)*ldc + col;
                    C[ro1]   = (sv[mt][nt][2]-mu1)*iv1*g0 + c0;
                    C[ro1+1] = (sv[mt][nt][3]-mu1)*iv1*g1 + c1;
                }
            }
        }
    } else if(EPI == 5){
        float p0[MT], p1[MT];
#pragma unroll
        for(int mt=0; mt<MT; mt++){ p0[mt]=0.f; p1[mt]=0.f; }
#pragma unroll
        for(int mt=0; mt<MT; mt++){
#pragma unroll
            for(int nt=0; nt<NT2; nt++){
                int col = wn0 + nt*8 + 2*tg;
                float b0 = bias[col], b1 = bias[col+1];
                float w0 = lns[col],  w1 = lns[col+1];
                float v0 = siluf(acc[mt][nt][0]+b0);
                float v1 = siluf(acc[mt][nt][1]+b1);
                float v2 = siluf(acc[mt][nt][2]+b0);
                float v3 = siluf(acc[mt][nt][3]+b1);
                p0[mt] += v0*w0 + v1*w1;
                p1[mt] += v2*w0 + v3*w1;
            }
        }
#pragma unroll
        for(int mt=0; mt<MT; mt++){
            p0[mt] += __shfl_xor_sync(0xffffffffu, p0[mt], 1);
            p0[mt] += __shfl_xor_sync(0xffffffffu, p0[mt], 2);
            p1[mt] += __shfl_xor_sync(0xffffffffu, p1[mt], 1);
            p1[mt] += __shfl_xor_sync(0xffffffffu, p1[mt], 2);
            if(tg == 0){
                int rr0 = wm0 + mt*16 + g;
                sEp[warp_n*BM + rr0]     = p0[mt];
                sEp[warp_n*BM + rr0 + 8] = p1[mt];
            }
        }
        __syncthreads();
        if(tid < BM){
            int grow = m0 + tid;
            if(grow < M){
                float v = 0.f;
#pragma unroll
                for(int wn = 0; wn < WARPS_N; wn++) v += sEp[wn*BM + tid];
                g_gate[grow] = v + lnb[0];
            }
        }
    } else {
#pragma unroll
        for(int mt=0; mt<MT; mt++){
#pragma unroll
            for(int nt=0; nt<NT2; nt++){
                int col = n0 + wn0 + nt*8 + 2*tg;
                float b0 = bias? bias[col]   : 0.f;
                float b1 = bias? bias[col+1] : 0.f;
                int row0 = m0 + wm0 + mt*16 + g;
                if(row0 < M){
                    float v0 = acc[mt][nt][0] + b0;
                    float v1 = acc[mt][nt][1] + b1;
                    if(EPI==1){ v0 = siluf(v0); v1 = siluf(v1); }
                    C[(size_t)row0*ldc + col]   = v0;
                    C[(size_t)row0*ldc + col+1] = v1;
                }
                int row1 = row0 + 8;
                if(row1 < M){
                    float v2 = acc[mt][nt][2] + b0;
                    float v3 = acc[mt][nt][3] + b1;
                    if(EPI==1){ v2 = siluf(v2); v3 = siluf(v3); }
                    C[(size_t)row1*ldc + col]   = v2;
                    C[(size_t)row1*ldc + col+1] = v3;
                }
            }
        }
    }
}

// ---------------- per-node softmax + aggregation + bias + silu + LN(256) ----------------
__global__ void k_aggregate(const int* __restrict__ src,
                            const float* __restrict__ xl,
                            const float* __restrict__ bias,
                            const float* __restrict__ ln1s, const float* __restrict__ ln1b,
                            float* __restrict__ out)
{
    __shared__ float sm4[4], sinv[4];
    __shared__ int   sS[32];
    __shared__ float sA[32*4];
    __shared__ float red[16];

    int n = blockIdx.x, tid = threadIdx.x, lane = tid&31, warp = tid>>5;
    int b = g_rowptr[n];
    int cnt = g_rowptr[n+1] - b;

    if(warp == 0){
        float mx[4] = {-1e30f,-1e30f,-1e30f,-1e30f};
        for(int j=lane; j<cnt; j+=32){
            int eid = g_csr[b+j];
#pragma unroll
            for(int h=0;h<4;h++) mx[h] = fmaxf(mx[h], g_logits[eid*4+h]);
        }
#pragma unroll
        for(int h=0;h<4;h++)
            for(int o=16;o;o>>=1) mx[h] = fmaxf(mx[h], __shfl_xor_sync(0xffffffffu, mx[h], o));
        float su[4] = {0.f,0.f,0.f,0.f};
        for(int j=lane; j<cnt; j+=32){
            int eid = g_csr[b+j];
#pragma unroll
            for(int h=0;h<4;h++) su[h] += __expf(g_logits[eid*4+h] - mx[h]);
        }
#pragma unroll
        for(int h=0;h<4;h++)
            for(int o=16;o;o>>=1) su[h] += __shfl_xor_sync(0xffffffffu, su[h], o);
        if(lane < 4){ sm4[lane] = mx[lane]; sinv[lane] = 1.f/(su[lane] + 1e-16f); }
    }
    __syncthreads();

    float a0=0.f, a1=0.f, a2=0.f, a3=0.f;
    int c = tid, h = c>>6;
    for(int base=0; base<cnt; base+=32){
        int jn = min(32, cnt-base);
        if(tid < 32 && lane < jn){
            int eid = g_csr[b+base+lane];
            sS[lane] = (eid < Ee) ? src[eid] : n;
#pragma unroll
            for(int hh=0; hh<4; hh++)
                sA[lane*4+hh] = __expf(g_logits[eid*4+hh] - sm4[hh]) * sinv[hh];
        }
        __syncthreads();
        int j = 0;
        for(; j+4<=jn; j+=4){
            a0 += sA[(j+0)*4+h] * xl[(size_t)sS[j+0]*LDB + c];
            a1 += sA[(j+1)*4+h] * xl[(size_t)sS[j+1]*LDB + c];
            a2 += sA[(j+2)*4+h] * xl[(size_t)sS[j+2]*LDB + c];
            a3 += sA[(j+3)*4+h] * xl[(size_t)sS[j+3]*LDB + c];
        }
        for(; j<jn; j++)
            a0 += sA[j*4+h] * xl[(size_t)sS[j]*LDB + c];
        __syncthreads();
    }
    float acc = (a0+a1)+(a2+a3);

    float v = siluf(acc + bias[c]);
    float s1 = v, s2 = v*v;
    for(int o=16;o;o>>=1){ s1 += __shfl_xor_sync(0xffffffffu,s1,o); s2 += __shfl_xor_sync(0xffffffffu,s2,o); }
    if(lane == 0){ red[warp] = s1; red[8+warp] = s2; }
    __syncthreads();
    if(warp == 0){
        float a = (lane<8)? red[lane]   : 0.f;
        float q = (lane<8)? red[8+lane] : 0.f;
        for(int o=4;o;o>>=1){ a += __shfl_xor_sync(0xffffffffu,a,o); q += __shfl_xor_sync(0xffffffffu,q,o); }
        if(lane == 0){ red[0]=a; red[8]=q; }
    }
    __syncthreads();
    float mu  = red[0]*(1.f/256.f);
    float var = red[8]*(1.f/256.f) - mu*mu;
    out[(size_t)n*1024 + c] = (v-mu)*rsqrtf(var+1e-5f)*ln1s[c] + ln1b[c];
}

// ---------------- per-graph pooling + head ----------------
__global__ void k_pool(const int* __restrict__ batch, const float* __restrict__ hW,
                       const float* __restrict__ hb, float* __restrict__ out){
    __shared__ int bnd[2];
    __shared__ float red[8];
    __shared__ float sstat[2];
    int g = blockIdx.x, tid = threadIdx.x, lane = tid&31, warp = tid>>5;
    if(tid < 2){
        int tgt = g + tid;
        int lo=0, hi=Nn;
        while(lo<hi){ int m=(lo+hi)>>1; if(batch[m]<tgt) lo=m+1; else hi=m; }
        bnd[tid]=lo;
    }
    __syncthreads();
    int lo=bnd[0], hi=bnd[1];

    float m = -1e30f;
    for(int i=lo+tid;i<hi;i+=256) m = fmaxf(m, g_gate[i]);
    for(int o=16;o;o>>=1) m = fmaxf(m, __shfl_xor_sync(0xffffffffu,m,o));
    if(lane==0) red[warp]=m;
    __syncthreads();
    if(tid==0){
        float v=red[0];
        for(int w2=1;w2<8;w2++) v = fmaxf(v, red[w2]);
        if(v < -1e29f) v = 0.f;
        sstat[0]=v;
    }
    __syncthreads();
    m = sstat[0];
    float sd = 0.f;
    for(int i=lo+tid;i<hi;i+=256) sd += __expf(g_gate[i]-m);
    for(int o=16;o;o>>=1) sd += __shfl_xor_sync(0xffffffffu,sd,o);
    if(lane==0) red[warp]=sd;
    __syncthreads();
    if(tid==0){
        float v=0.f;
        for(int w2=0;w2<8;w2++) v += red[w2];
        sstat[1] = 1.f/(v+1e-16f);
    }
    __syncthreads();
    float inv = sstat[1];
    float acc = 0.f;
    for(int i=lo;i<hi;i++){
        float w2 = __expf(g_gate[i]-m)*inv;
        acc += w2 * g_hfin[(size_t)i*256+tid];
    }
    float pv = acc*hW[tid];
    for(int o=16;o;o>>=1) pv += __shfl_xor_sync(0xffffffffu,pv,o);
    if(lane==0) red[warp]=pv;
    __syncthreads();
    if(tid==0){
        float v=0.f;
        for(int w2=0;w2<8;w2++) v += red[w2];
        out[g] = v + hb[0];
    }
}

// ---------------- host ----------------
extern "C" void kernel_launch(void* const* d_in, const int* in_sizes, int n_in,
                              void* d_out, int out_size){
    const float* x     = (const float*)d_in[0];
    const int*   ei    = (const int*)  d_in[1];
    const float* eattr = (const float*)d_in[2];
    const int*   batch = (const int*)  d_in[3];
    const float* atomW = (const float*)d_in[4];
    const float* atomB = (const float*)d_in[5];
    const float* bondW = (const float*)d_in[6];
    const float* bondB = (const float*)d_in[7];
    const float* Wl    = (const float*)d_in[8];
    const float* bl    = (const float*)d_in[9];
    const float* Wr    = (const float*)d_in[10];
    const float* br    = (const float*)d_in[11];
    const float* We    = (const float*)d_in[12];
    const float* att   = (const float*)d_in[13];
    const float* bias  = (const float*)d_in[14];
    const float* ln1s  = (const float*)d_in[15];
    const float* ln1b  = (const float*)d_in[16];
    const float* eW    = (const float*)d_in[17];
    const float* eb    = (const float*)d_in[18];
    const float* ln2s  = (const float*)d_in[19];
    const float* ln2b  = (const float*)d_in[20];
    const float* jkW   = (const float*)d_in[21];
    const float* jkb   = (const float*)d_in[22];
    const float* ln3s  = (const float*)d_in[23];
    const float* ln3b  = (const float*)d_in[24];
    const float* gW1   = (const float*)d_in[25];
    const float* gb1   = (const float*)d_in[26];
    const float* gW2   = (const float*)d_in[27];
    const float* gb2   = (const float*)d_in[28];
    const float* hW    = (const float*)d_in[29];
    const float* hb    = (const float*)d_in[30];
    float* out = (float*)d_out;

    const int* src = ei;
    const int* dst = ei + Ee;

    float *h0p, *eAp, *eBp, *bigp, *pqp, *hjkp, *hfinp, *logp, *wpk, *bpk, *wpq;
    int *srcxp, *dstxp;
    cudaGetSymbolAddress((void**)&h0p,   g_h0);
    cudaGetSymbolAddress((void**)&eAp,   g_eA);
    cudaGetSymbolAddress((void**)&eBp,   g_eB);
    cudaGetSymbolAddress((void**)&bigp,  g_big);
    cudaGetSymbolAddress((void**)&pqp,   g_pq);
    cudaGetSymbolAddress((void**)&hjkp,  g_hjk);
    cudaGetSymbolAddress((void**)&hfinp, g_hfin);
    cudaGetSymbolAddress((void**)&logp,  g_logits);
    cudaGetSymbolAddress((void**)&wpk,   g_wpack);
    cudaGetSymbolAddress((void**)&bpk,   g_bpack);
    cudaGetSymbolAddress((void**)&wpq,   g_wpq);
    cudaGetSymbolAddress((void**)&srcxp, g_srcx);
    cudaGetSymbolAddress((void**)&dstxp, g_dstx);

    static cudaStream_t s2 = nullptr;
    static cudaEvent_t evFork, evP, evCSR, evL[4], evA[3];
    if(!s2){
        cudaStreamCreateWithFlags(&s2, cudaStreamNonBlocking);
        cudaEventCreateWithFlags(&evFork, cudaEventDisableTiming);
        cudaEventCreateWithFlags(&evP,    cudaEventDisableTiming);
        cudaEventCreateWithFlags(&evCSR,  cudaEventDisableTiming);
        for(int i=0;i<4;i++) cudaEventCreateWithFlags(&evL[i], cudaEventDisableTiming);
        for(int i=0;i<3;i++) cudaEventCreateWithFlags(&evA[i], cudaEventDisableTiming);
    }

    // ---- fork s2 off the main (captured) stream ----
    cudaEventRecord(evFork, 0);
    cudaStreamWaitEvent(s2, evFork, 0);

    // s2: encoders + weight packing + extidx
    k_atom_enc<<<(Nn*Dd+255)/256,256,0,s2>>>(x, atomW, atomB);
    k_bond_enc<<<(Ee*EDd+255)/256,256,0,s2>>>(eattr, bondW, bondB);
    k_pack<<<(4*Dd*LDB+255)/256,256,0,s2>>>(Wl, Wr);
    k_packpq<<<(4*Dd*128+255)/256,256,0,s2>>>(eW);
    k_packb<<<(4*LDB+255)/256,256,0,s2>>>(bl, br);
    k_extidx<<<(ENt+255)/256,256,0,s2>>>(src, dst);
    cudaEventRecord(evP, s2);

    // s1: CSR build (multi-block scan)
    k_zero_deg<<<(Nn+255)/256,256>>>();
    k_deg <<<(Ee+255)/256,256>>>(dst);
    k_scan_local<<<20,1024>>>();
    k_scan_off<<<1,32>>>();
    k_scan_add<<<(Nn+255)/256,256>>>();
    k_fill<<<(Ee+255)/256,256>>>(dst);
    k_selfloop<<<(Nn+255)/256,256>>>();
    cudaEventRecord(evCSR, 0);

    // s2: loope(0)
    cudaStreamWaitEvent(s2, evCSR, 0);
    k_loope<<<Nn,64,0,s2>>>(eAp);
    cudaEventRecord(evL[0], s2);

    cudaStreamWaitEvent(0, evP, 0);

    for(int l=0; l<4; l++){
        float* e_cur  = (l&1) ? eBp : eAp;
        float* e_next = (l&1) ? eAp : eBp;
        const float* hcur = (l==0) ? h0p : (hjkp + (l-1)*256);
        int ldh = (l==0) ? 256 : 1024;

        // s1: packed node GEMM [xl|xr] = hcur @ [Wl|Wr]
        dim3 gN(LDB/128, (Nn+127)/128);
        mma_gemm<128,128,16,64,32,0,0><<<gN,256>>>(
            hcur, ldh, wpk + l*Dd*LDB, LDB, bpk + l*LDB, bigp, LDB, Nn, 256,
            nullptr,nullptr,nullptr,nullptr, nullptr,nullptr, 0);

        cudaStreamWaitEvent(0, evL[l], 0);

        // s1: logits
        dim3 gL(2,(ENt+127)/128);
        mma_gemm<128,128,16,64,32,1,3><<<gL,256>>>(
            e_cur, 64, We + l*EDd*Dd, 256, nullptr, logp, 4, ENt, 64,
            bigp, bigp + 256, srcxp, dstxp, att + l*256, nullptr, LDB);

        // s1: aggregate
        k_aggregate<<<Nn,256>>>(src, bigp, bias + l*256, ln1s + l*256, ln1b + l*256,
                                hjkp + l*256);

        if(l < 3){
            cudaEventRecord(evA[l], 0);
            // s2: edge path
            cudaStreamWaitEvent(s2, evA[l], 0);
            dim3 gPQ(1,(Nn+127)/128);
            mma_gemm<128,128,16,64,32,0,0><<<gPQ,256,0,s2>>>(
                hjkp + l*256, 1024, wpq + l*Dd*128, 128, nullptr, pqp, 128, Nn, 256,
                nullptr,nullptr,nullptr,nullptr, nullptr,nullptr, 0);
            dim3 gE(1, Ee/128);
            mma_gemm<128,64,16,32,32,0,4><<<gE,256,0,s2>>>(
                e_cur, 64, eW + l*576*64 + 512*64, 64, eb + l*64, e_next, 64, Ee, 64,
                pqp, nullptr, src, dst, ln2s + l*64, ln2b + l*64, 128);
            k_loope<<<Nn,64,0,s2>>>(e_next);
            cudaEventRecord(evL[l+1], s2);
        }
    }

    // tail on s1: JK GEMM with fused silu+LN(256) epilogue (full-row blocks)
    dim3 gJK(1,(Nn+63)/64);
    mma_gemm<64,256,16,32,64,0,7><<<gJK,256>>>(
        hjkp, 1024, jkW, 256, jkb, hfinp, 256, Nn, 1024,
        nullptr,nullptr,nullptr,nullptr, ln3s, ln3b, 0);

    dim3 gG1(1,(Nn+127)/128);
    mma_gemm<128,128,16,64,32,0,5><<<gG1,256>>>(
        hfinp, 256, gW1, 128, gb1, nullptr, 0, Nn, 256,
        nullptr,nullptr,nullptr,nullptr, gW2, gb2, 0);

    k_pool<<<Gg,256>>>(batch, hW, hb, out);
}

// round 16
// speedup vs baseline: 1.1112x; 1.0011x over previous
#include <cuda_runtime.h>
#include <math.h>
#include <stdint.h>

#define Nn 20000
#define Ee 320000
#define ENt 340000
#define Gg 128
#define Dd 256
#define EDd 64
#define LDB 512

// ---------------- static scratch ----------------
__device__ float g_h0[Nn*Dd];
__device__ float g_eA[Ee*EDd];
__device__ float g_eB[Ee*EDd];
__device__ float g_loope[Nn*EDd];
__device__ float g_big[Nn*LDB];          // [xl | xr] stride 512
__device__ float g_pq[Nn*128];           // [P | Q] stride 128
__device__ float g_logits[ENt*4];
__device__ float g_hjk[Nn*Dd*4];
__device__ float g_hfin[Nn*Dd];
__device__ float g_gate[Nn];
__device__ float g_wpack[4*Dd*LDB];
__device__ float g_bpack[4*LDB];
__device__ float g_wpq[4*Dd*128];
__device__ int   g_deg[Nn];
__device__ int   g_rowptr[Nn+1];
__device__ int   g_fill[Nn];
__device__ int   g_csr[ENt];
__device__ int   g_srcx[ENt];
__device__ int   g_dstx[ENt];
__device__ int   g_bsum[20];

__device__ __forceinline__ float siluf(float v){ return v/(1.f+__expf(-v)); }

__device__ __forceinline__ uint32_t f2tf32(float f){
    uint32_t r;
    asm("cvt.rna.tf32.f32 %0, %1;" : "=r"(r) : "f"(f));
    return r;
}

// ---------------- init / encoders / packing ----------------
__global__ void k_zero_deg(){
    int i = blockIdx.x*blockDim.x + threadIdx.x;
    if(i < Nn) g_deg[i] = 0;
}

__global__ void k_atom_enc(const float* __restrict__ x, const float* __restrict__ W,
                           const float* __restrict__ b){
    int idx = blockIdx.x*blockDim.x + threadIdx.x;
    if(idx >= Nn*Dd) return;
    int n = idx >> 8, c = idx & 255;
    float acc = b[c];
#pragma unroll
    for(int k=0;k<9;k++) acc += x[n*9+k]*W[k*Dd+c];
    g_h0[idx] = acc;
}

__global__ void k_bond_enc(const float* __restrict__ ea, const float* __restrict__ W,
                           const float* __restrict__ b){
    int idx = blockIdx.x*blockDim.x + threadIdx.x;
    if(idx >= Ee*EDd) return;
    int e = idx >> 6, c = idx & 63;
    float acc = b[c];
#pragma unroll
    for(int k=0;k<3;k++) acc += ea[e*3+k]*W[k*EDd+c];
    g_eA[idx] = acc;
}

__global__ void k_pack(const float* __restrict__ Wl, const float* __restrict__ Wr){
    int idx = blockIdx.x*blockDim.x + threadIdx.x;
    if(idx >= 4*Dd*LDB) return;
    int l = idx/(Dd*LDB);
    int r = (idx/LDB)%Dd;
    int n = idx%LDB;
    g_wpack[idx] = (n < 256) ? Wl[l*65536 + r*256 + n] : Wr[l*65536 + r*256 + (n-256)];
}

__global__ void k_packpq(const float* __restrict__ eW){
    int idx = blockIdx.x*blockDim.x + threadIdx.x;
    if(idx >= 4*Dd*128) return;
    int l = idx/(Dd*128);
    int r = (idx/128)%Dd;
    int n = idx%128;
    g_wpq[idx] = (n < 64) ? eW[l*36864 + r*64 + n] : eW[l*36864 + (256+r)*64 + (n-64)];
}

__global__ void k_packb(const float* __restrict__ bl, const float* __restrict__ br){
    int idx = blockIdx.x*blockDim.x + threadIdx.x;
    if(idx >= 4*LDB) return;
    int l = idx/LDB, n = idx%LDB;
    g_bpack[idx] = (n<256) ? bl[l*256+n] : br[l*256+(n-256)];
}

__global__ void k_extidx(const int* __restrict__ src, const int* __restrict__ dst){
    int i = blockIdx.x*blockDim.x + threadIdx.x;
    if(i >= ENt) return;
    if(i < Ee){ g_srcx[i] = src[i]; g_dstx[i] = dst[i]; }
    else      { g_srcx[i] = g_dstx[i] = i - Ee; }
}

// ---------------- CSR by dst (multi-block scan) ----------------
__global__ void k_deg(const int* __restrict__ dst){
    int e = blockIdx.x*blockDim.x + threadIdx.x;
    if(e < Ee) atomicAdd(&g_deg[dst[e]], 1);
}

__global__ void k_scan_local(){
    __shared__ int sd[1024];
    int b = blockIdx.x, tid = threadIdx.x;
    int i = b*1024 + tid;
    int v = (i < Nn) ? (g_deg[i] + 1) : 0;
    sd[tid] = v; __syncthreads();
    for(int off=1; off<1024; off<<=1){
        int t = (tid >= off) ? sd[tid-off] : 0;
        __syncthreads();
        sd[tid] += t; __syncthreads();
    }
    if(i < Nn) g_rowptr[i+1] = sd[tid];
    if(tid == 1023) g_bsum[b] = sd[1023];
}

__global__ void k_scan_off(){
    if(threadIdx.x == 0){
        int acc = 0;
        for(int b=0;b<20;b++){ int t = g_bsum[b]; g_bsum[b] = acc; acc += t; }
        g_rowptr[0] = 0;
    }
}

__global__ void k_scan_add(){
    int i = blockIdx.x*blockDim.x + threadIdx.x;
    if(i < Nn){
        int r = g_rowptr[i+1] + g_bsum[i>>10];
        g_rowptr[i+1] = r;
        g_fill[i] = r - (g_deg[i] + 1);
    }
}

__global__ void k_fill(const int* __restrict__ dst){
    int e = blockIdx.x*blockDim.x + threadIdx.x;
    if(e < Ee){ int p = atomicAdd(&g_fill[dst[e]], 1); g_csr[p] = e; }
}

__global__ void k_selfloop(){
    int n = blockIdx.x*blockDim.x + threadIdx.x;
    if(n < Nn) g_csr[g_rowptr[n+1]-1] = Ee + n;
}

__global__ void k_loope(const float* __restrict__ e){
    int n = blockIdx.x;
    int tid = threadIdx.x;           // 64 threads
    int b = g_rowptr[n];
    int cnt = g_rowptr[n+1] - 1 - b;
    float acc = 0.f;
    for(int j=0;j<cnt;j++){
        int eid = g_csr[b+j];
        acc += e[(size_t)eid*EDd + tid];
    }
    g_loope[n*EDd + tid] = acc / (float)max(cnt, 1);
}

// ---------------- tf32 tensor-core GEMM, double-buffered ----------------
// GMODE: 0 = plain A; 1 = rows < Ee from A, rows >= Ee from g_loope
// EPI: 0 = +bias; 1 = +bias+silu
//      3 = GATv2 logits epilogue -> C=[M,4]
//      4 = edge MLP epilogue (silu+LN64)
//      5 = gate epilogue -> g_gate[row]
//      7 = +bias+silu+LayerNorm(BN) fused (full-row blocks, row-guarded)
template<int BM,int BN,int BK,int WM,int WN,int GMODE,int EPI>
__global__ void mma_gemm(const float* __restrict__ A, int lda,
                         const float* __restrict__ B, int ldb,
                         const float* __restrict__ bias,
                         float* __restrict__ C, int ldc,
                         int M, int K,
                         const float* __restrict__ aux1,
                         const float* __restrict__ aux2,
                         const int* __restrict__ srcv, const int* __restrict__ dstv,
                         const float* __restrict__ lns, const float* __restrict__ lnb,
                         int ldx)
{
    constexpr int WARPS_N = BN/WN, WARPS_M = BM/WM;
    constexpr int NTHREADS = WARPS_M*WARPS_N*32;
    constexpr int MT = WM/16, NT2 = WN/8;
    constexpr int PAD = 8;
    __shared__ uint32_t As[2][BK][BM+PAD];
    __shared__ uint32_t Bs[2][BK][BN+PAD];
    __shared__ int sSrc[(EPI==3||EPI==4)?BM:1];
    __shared__ int sDst[(EPI==3||EPI==4)?BM:1];
    __shared__ float sEp[(EPI==7)?2*WARPS_N*BM : ((EPI>=3)?4*BM:1)];

    int tid = threadIdx.x;
    int m0 = blockIdx.y*BM, n0 = blockIdx.x*BN;

    if(EPI == 3 || EPI == 4){
        for(int t=tid; t<BM; t+=NTHREADS){
            int r = m0 + t;
            sSrc[t] = (r < M) ? srcv[r] : 0;
            sDst[t] = (r < M) ? dstv[r] : 0;
        }
        __syncthreads();
    }

    int warp = tid>>5, lane = tid&31;
    int warp_n = warp % WARPS_N, warp_m = warp / WARPS_N;
    int wm0 = warp_m*WM, wn0 = warp_n*WN;
    int g = lane>>2, tg = lane&3;

    float acc[MT][NT2][4];
#pragma unroll
    for(int i=0;i<MT;i++)
#pragma unroll
        for(int j=0;j<NT2;j++)
#pragma unroll
            for(int q=0;q<4;q++) acc[i][j][q] = 0.f;

    constexpr int AV = (BM*BK/4)/NTHREADS;
    constexpr int BV = (BK*BN/4)/NTHREADS;
    float4 ra[AV], rb[BV];

    auto load_g = [&](int k0){
#pragma unroll
        for(int it=0; it<AV; it++){
            int u = tid + it*NTHREADS;
            int r = u/(BK/4), kq = u%(BK/4);
            int k = k0 + kq*4;
            int grow = m0 + r;
            float4 v;
            if(GMODE == 1){
                if(grow < Ee)       v = *(const float4*)(A + (size_t)grow*64 + k);
                else if(grow < M)   v = *(const float4*)(g_loope + (size_t)(grow-Ee)*64 + k);
                else                v = make_float4(0.f,0.f,0.f,0.f);
            } else {
                if(grow < M) v = *(const float4*)(A + (size_t)grow*lda + k);
                else         v = make_float4(0.f,0.f,0.f,0.f);
            }
            ra[it] = v;
        }
#pragma unroll
        for(int it=0; it<BV; it++){
            int u = tid + it*NTHREADS;
            int kk = u/(BN/4), cq = u%(BN/4);
            rb[it] = *(const float4*)(B + (size_t)(k0+kk)*ldb + n0 + cq*4);
        }
    };
    auto store_s = [&](int buf){
#pragma unroll
        for(int it=0; it<AV; it++){
            int u = tid + it*NTHREADS;
            int r = u/(BK/4), kq = u%(BK/4);
            As[buf][kq*4+0][r]=f2tf32(ra[it].x); As[buf][kq*4+1][r]=f2tf32(ra[it].y);
            As[buf][kq*4+2][r]=f2tf32(ra[it].z); As[buf][kq*4+3][r]=f2tf32(ra[it].w);
        }
#pragma unroll
        for(int it=0; it<BV; it++){
            int u = tid + it*NTHREADS;
            int kk = u/(BN/4), cq = u%(BN/4);
            Bs[buf][kk][cq*4+0]=f2tf32(rb[it].x); Bs[buf][kk][cq*4+1]=f2tf32(rb[it].y);
            Bs[buf][kk][cq*4+2]=f2tf32(rb[it].z); Bs[buf][kk][cq*4+3]=f2tf32(rb[it].w);
        }
    };

    load_g(0);
    store_s(0);
    __syncthreads();

    int T = K/BK;
    for(int kt=0; kt<T; kt++){
        if(kt+1 < T) load_g((kt+1)*BK);
        int buf = kt & 1;
#pragma unroll
        for(int ks=0; ks<BK/8; ks++){
            uint32_t af[MT][4], bf[NT2][2];
#pragma unroll
            for(int mt=0; mt<MT; mt++){
                int row = wm0 + mt*16 + g;
                af[mt][0] = As[buf][ks*8+tg  ][row];
                af[mt][1] = As[buf][ks*8+tg  ][row+8];
                af[mt][2] = As[buf][ks*8+tg+4][row];
                af[mt][3] = As[buf][ks*8+tg+4][row+8];
            }
#pragma unroll
            for(int nt=0; nt<NT2; nt++){
                int col = wn0 + nt*8 + g;
                bf[nt][0] = Bs[buf][ks*8+tg  ][col];
                bf[nt][1] = Bs[buf][ks*8+tg+4][col];
            }
#pragma unroll
            for(int mt=0; mt<MT; mt++)
#pragma unroll
                for(int nt=0; nt<NT2; nt++){
                    asm volatile(
                        "mma.sync.aligned.m16n8k8.row.col.f32.tf32.tf32.f32 "
                        "{%0,%1,%2,%3}, {%4,%5,%6,%7}, {%8,%9}, {%0,%1,%2,%3};"
                        : "+f"(acc[mt][nt][0]), "+f"(acc[mt][nt][1]),
                          "+f"(acc[mt][nt][2]), "+f"(acc[mt][nt][3])
                        : "r"(af[mt][0]), "r"(af[mt][1]), "r"(af[mt][2]), "r"(af[mt][3]),
                          "r"(bf[nt][0]), "r"(bf[nt][1]));
                }
        }
        if(kt+1 < T){
            store_s((kt+1)&1);
            __syncthreads();
        }
    }

    if(EPI == 3){
        float l0[MT], l1[MT];
#pragma unroll
        for(int mt=0; mt<MT; mt++){ l0[mt]=0.f; l1[mt]=0.f; }
#pragma unroll
        for(int mt=0; mt<MT; mt++){
            int rr0 = wm0 + mt*16 + g, rr1 = rr0 + 8;
            int s0 = sSrc[rr0], d0 = sDst[rr0];
            int s1 = sSrc[rr1], d1 = sDst[rr1];
#pragma unroll
            for(int nt=0; nt<NT2; nt++){
                int gc = n0 + wn0 + nt*8 + 2*tg;
                float a0 = lns[gc], a1 = lns[gc+1];
                float2 xs0 = *(const float2*)&aux1[(size_t)s0*ldx + gc];
                float2 xd0 = *(const float2*)&aux2[(size_t)d0*ldx + gc];
                float2 xs1 = *(const float2*)&aux1[(size_t)s1*ldx + gc];
                float2 xd1 = *(const float2*)&aux2[(size_t)d1*ldx + gc];
                float m00 = acc[mt][nt][0] + xs0.x + xd0.x; m00 = m00>0.f? m00 : 0.2f*m00;
                float m01 = acc[mt][nt][1] + xs0.y + xd0.y; m01 = m01>0.f? m01 : 0.2f*m01;
                float m10 = acc[mt][nt][2] + xs1.x + xd1.x; m10 = m10>0.f? m10 : 0.2f*m10;
                float m11 = acc[mt][nt][3] + xs1.y + xd1.y; m11 = m11>0.f? m11 : 0.2f*m11;
                l0[mt] += m00*a0 + m01*a1;
                l1[mt] += m10*a0 + m11*a1;
            }
        }
#pragma unroll
        for(int mt=0; mt<MT; mt++){
            l0[mt] += __shfl_xor_sync(0xffffffffu, l0[mt], 1);
            l0[mt] += __shfl_xor_sync(0xffffffffu, l0[mt], 2);
            l1[mt] += __shfl_xor_sync(0xffffffffu, l1[mt], 1);
            l1[mt] += __shfl_xor_sync(0xffffffffu, l1[mt], 2);
            if(tg == 0){
                int rr0 = wm0 + mt*16 + g;
                sEp[warp_n*BM + rr0]     = l0[mt];
                sEp[warp_n*BM + rr0 + 8] = l1[mt];
            }
        }
        __syncthreads();
        int row = tid & (BM-1), hh = tid >> 7;
        int grow = m0 + row;
        if(grow < M){
            float v = sEp[(2*hh)*BM + row] + sEp[(2*hh+1)*BM + row];
            C[(size_t)grow*4 + (n0>>6) + hh] = v;
        }
    } else if(EPI == 4){
        float sv[MT][NT2][4];
        float s1a[MT], s2a[MT], s1b[MT], s2b[MT];
#pragma unroll
        for(int mt=0; mt<MT; mt++){ s1a[mt]=s2a[mt]=s1b[mt]=s2b[mt]=0.f; }
#pragma unroll
        for(int mt=0; mt<MT; mt++){
            int rr0 = wm0 + mt*16 + g, rr1 = rr0 + 8;
            int s0 = sSrc[rr0], d0 = sDst[rr0];
            int s1i = sSrc[rr1], d1i = sDst[rr1];
#pragma unroll
            for(int nt=0; nt<NT2; nt++){
                int col = wn0 + nt*8 + 2*tg;
                float b0 = bias[col], b1 = bias[col+1];
                float2 p0 = *(const float2*)&aux1[(size_t)s0*ldx + col];
                float2 q0 = *(const float2*)&aux1[(size_t)d0*ldx + 64 + col];
                float2 p1 = *(const float2*)&aux1[(size_t)s1i*ldx + col];
                float2 q1 = *(const float2*)&aux1[(size_t)d1i*ldx + 64 + col];
                float v0 = siluf(acc[mt][nt][0]+b0+p0.x+q0.x);
                float v1 = siluf(acc[mt][nt][1]+b1+p0.y+q0.y);
                float v2 = siluf(acc[mt][nt][2]+b0+p1.x+q1.x);
                float v3 = siluf(acc[mt][nt][3]+b1+p1.y+q1.y);
                sv[mt][nt][0]=v0; sv[mt][nt][1]=v1; sv[mt][nt][2]=v2; sv[mt][nt][3]=v3;
                s1a[mt]+=v0+v1; s2a[mt]+=v0*v0+v1*v1;
                s1b[mt]+=v2+v3; s2b[mt]+=v2*v2+v3*v3;
            }
        }
#pragma unroll
        for(int mt=0; mt<MT; mt++){
#pragma unroll
            for(int o=1;o<4;o<<=1){
                s1a[mt] += __shfl_xor_sync(0xffffffffu, s1a[mt], o);
                s2a[mt] += __shfl_xor_sync(0xffffffffu, s2a[mt], o);
                s1b[mt] += __shfl_xor_sync(0xffffffffu, s1b[mt], o);
                s2b[mt] += __shfl_xor_sync(0xffffffffu, s2b[mt], o);
            }
            if(tg == 0){
                int r0 = wm0 + mt*16 + g;
                sEp[(warp_n*BM + r0)*2+0]   = s1a[mt];
                sEp[(warp_n*BM + r0)*2+1]   = s2a[mt];
                sEp[(warp_n*BM + r0+8)*2+0] = s1b[mt];
                sEp[(warp_n*BM + r0+8)*2+1] = s2b[mt];
            }
        }
        __syncthreads();
#pragma unroll
        for(int mt=0; mt<MT; mt++){
            int r0 = wm0 + mt*16 + g;
            float t1 = sEp[r0*2+0] + sEp[(BM+r0)*2+0];
            float t2 = sEp[r0*2+1] + sEp[(BM+r0)*2+1];
            float mu0 = t1*(1.f/BN);
            float iv0 = rsqrtf(t2*(1.f/BN)-mu0*mu0 + 1e-5f);
            int r1 = r0+8;
            float u1 = sEp[r1*2+0] + sEp[(BM+r1)*2+0];
            float u2 = sEp[r1*2+1] + sEp[(BM+r1)*2+1];
            float mu1 = u1*(1.f/BN);
            float iv1 = rsqrtf(u2*(1.f/BN)-mu1*mu1 + 1e-5f);
#pragma unroll
            for(int nt=0; nt<NT2; nt++){
                int col = wn0 + nt*8 + 2*tg;
                float g0 = lns[col], g1 = lns[col+1];
                float c0 = lnb[col], c1 = lnb[col+1];
                size_t ro0 = (size_t)(m0+r0)*ldc + col;
                size_t ro1 = (size_t)(m0+r1)*ldc + col;
                C[ro0]   = (sv[mt][nt][0]-mu0)*iv0*g0 + c0;
                C[ro0+1] = (sv[mt][nt][1]-mu0)*iv0*g1 + c1;
                C[ro1]   = (sv[mt][nt][2]-mu1)*iv1*g0 + c0;
                C[ro1+1] = (sv[mt][nt][3]-mu1)*iv1*g1 + c1;
            }
        }
    } else if(EPI == 7){
        // bias + silu + LayerNorm(BN) with full row per block (WARPS_N partial sums)
        float sv[MT][NT2][4];
        float s1a[MT], s2a[MT], s1b[MT], s2b[MT];
#pragma unroll
        for(int mt=0; mt<MT; mt++){ s1a[mt]=s2a[mt]=s1b[mt]=s2b[mt]=0.f; }
#pragma unroll
        for(int mt=0; mt<MT; mt++){
#pragma unroll
            for(int nt=0; nt<NT2; nt++){
                int col = wn0 + nt*8 + 2*tg;
                float b0 = bias[col], b1 = bias[col+1];
                float v0 = siluf(acc[mt][nt][0]+b0);
                float v1 = siluf(acc[mt][nt][1]+b1);
                float v2 = siluf(acc[mt][nt][2]+b0);
                float v3 = siluf(acc[mt][nt][3]+b1);
                sv[mt][nt][0]=v0; sv[mt][nt][1]=v1; sv[mt][nt][2]=v2; sv[mt][nt][3]=v3;
                s1a[mt]+=v0+v1; s2a[mt]+=v0*v0+v1*v1;
                s1b[mt]+=v2+v3; s2b[mt]+=v2*v2+v3*v3;
            }
        }
#pragma unroll
        for(int mt=0; mt<MT; mt++){
#pragma unroll
            for(int o=1;o<4;o<<=1){
                s1a[mt] += __shfl_xor_sync(0xffffffffu, s1a[mt], o);
                s2a[mt] += __shfl_xor_sync(0xffffffffu, s2a[mt], o);
                s1b[mt] += __shfl_xor_sync(0xffffffffu, s1b[mt], o);
                s2b[mt] += __shfl_xor_sync(0xffffffffu, s2b[mt], o);
            }
            if(tg == 0){
                int r0 = wm0 + mt*16 + g;
                sEp[(warp_n*BM + r0)*2+0]   = s1a[mt];
                sEp[(warp_n*BM + r0)*2+1]   = s2a[mt];
                sEp[(warp_n*BM + r0+8)*2+0] = s1b[mt];
                sEp[(warp_n*BM + r0+8)*2+1] = s2b[mt];
            }
        }
        __syncthreads();
#pragma unroll
        for(int mt=0; mt<MT; mt++){
            int r0 = wm0 + mt*16 + g;
            int r1 = r0+8;
            float t1=0.f,t2=0.f,u1=0.f,u2=0.f;
#pragma unroll
            for(int wn=0; wn<WARPS_N; wn++){
                t1 += sEp[(wn*BM + r0)*2+0];
                t2 += sEp[(wn*BM + r0)*2+1];
                u1 += sEp[(wn*BM + r1)*2+0];
                u2 += sEp[(wn*BM + r1)*2+1];
            }
            float mu0 = t1*(1.f/BN);
            float iv0 = rsqrtf(t2*(1.f/BN)-mu0*mu0 + 1e-5f);
            float mu1 = u1*(1.f/BN);
            float iv1 = rsqrtf(u2*(1.f/BN)-mu1*mu1 + 1e-5f);
            bool ok0 = (m0+r0) < M, ok1 = (m0+r1) < M;
#pragma unroll
            for(int nt=0; nt<NT2; nt++){
                int col = wn0 + nt*8 + 2*tg;
                float g0 = lns[col], g1 = lns[col+1];
                float c0 = lnb[col], c1 = lnb[col+1];
                if(ok0){
                    size_t ro0 = (size_t)(m0+r0)*ldc + col;
                    C[ro0]   = (sv[mt][nt][0]-mu0)*iv0*g0 + c0;
                    C[ro0+1] = (sv[mt][nt][1]-mu0)*iv0*g1 + c1;
                }
                if(ok1){
                    size_t ro1 = (size_t)(m0+r1)*ldc + col;
                    C[ro1]   = (sv[mt][nt][2]-mu1)*iv1*g0 + c0;
                    C[ro1+1] = (sv[mt][nt][3]-mu1)*iv1*g1 + c1;
                }
            }
        }
    } else if(EPI == 5){
        float p0[MT], p1[MT];
#pragma unroll
        for(int mt=0; mt<MT; mt++){ p0[mt]=0.f; p1[mt]=0.f; }
#pragma unroll
        for(int mt=0; mt<MT; mt++){
#pragma unroll
            for(int nt=0; nt<NT2; nt++){
                int col = wn0 + nt*8 + 2*tg;
                float b0 = bias[col], b1 = bias[col+1];
                float w0 = lns[col],  w1 = lns[col+1];
                float v0 = siluf(acc[mt][nt][0]+b0);
                float v1 = siluf(acc[mt][nt][1]+b1);
                float v2 = siluf(acc[mt][nt][2]+b0);
                float v3 = siluf(acc[mt][nt][3]+b1);
                p0[mt] += v0*w0 + v1*w1;
                p1[mt] += v2*w0 + v3*w1;
            }
        }
#pragma unroll
        for(int mt=0; mt<MT; mt++){
            p0[mt] += __shfl_xor_sync(0xffffffffu, p0[mt], 1);
            p0[mt] += __shfl_xor_sync(0xffffffffu, p0[mt], 2);
            p1[mt] += __shfl_xor_sync(0xffffffffu, p1[mt], 1);
            p1[mt] += __shfl_xor_sync(0xffffffffu, p1[mt], 2);
            if(tg == 0){
                int rr0 = wm0 + mt*16 + g;
                sEp[warp_n*BM + rr0]     = p0[mt];
                sEp[warp_n*BM + rr0 + 8] = p1[mt];
            }
        }
        __syncthreads();
        if(tid < BM){
            int grow = m0 + tid;
            if(grow < M){
                float v = 0.f;
#pragma unroll
                for(int wn = 0; wn < WARPS_N; wn++) v += sEp[wn*BM + tid];
                g_gate[grow] = v + lnb[0];
            }
        }
    } else {
#pragma unroll
        for(int mt=0; mt<MT; mt++){
#pragma unroll
            for(int nt=0; nt<NT2; nt++){
                int col = n0 + wn0 + nt*8 + 2*tg;
                float b0 = bias? bias[col]   : 0.f;
                float b1 = bias? bias[col+1] : 0.f;
                int row0 = m0 + wm0 + mt*16 + g;
                if(row0 < M){
                    float v0 = acc[mt][nt][0] + b0;
                    float v1 = acc[mt][nt][1] + b1;
                    if(EPI==1){ v0 = siluf(v0); v1 = siluf(v1); }
                    C[(size_t)row0*ldc + col]   = v0;
                    C[(size_t)row0*ldc + col+1] = v1;
                }
                int row1 = row0 + 8;
                if(row1 < M){
                    float v2 = acc[mt][nt][2] + b0;
                    float v3 = acc[mt][nt][3] + b1;
                    if(EPI==1){ v2 = siluf(v2); v3 = siluf(v3); }
                    C[(size_t)row1*ldc + col]   = v2;
                    C[(size_t)row1*ldc + col+1] = v3;
                }
            }
        }
    }
}

// ---------------- per-node softmax + aggregation + bias + silu + LN(256) ----------------
__global__ void k_aggregate(const int* __restrict__ src,
                            const float* __restrict__ xl,
                            const float* __restrict__ bias,
                            const float* __restrict__ ln1s, const float* __restrict__ ln1b,
                            float* __restrict__ out)
{
    __shared__ float sm4[4], sinv[4];
    __shared__ int   sS[32];
    __shared__ float sA[32*4];
    __shared__ float red[16];

    int n = blockIdx.x, tid = threadIdx.x, lane = tid&31, warp = tid>>5;
    int b = g_rowptr[n];
    int cnt = g_rowptr[n+1] - b;

    if(warp == 0){
        float mx[4] = {-1e30f,-1e30f,-1e30f,-1e30f};
        for(int j=lane; j<cnt; j+=32){
            int eid = g_csr[b+j];
#pragma unroll
            for(int h=0;h<4;h++) mx[h] = fmaxf(mx[h], g_logits[eid*4+h]);
        }
#pragma unroll
        for(int h=0;h<4;h++)
            for(int o=16;o;o>>=1) mx[h] = fmaxf(mx[h], __shfl_xor_sync(0xffffffffu, mx[h], o));
        float su[4] = {0.f,0.f,0.f,0.f};
        for(int j=lane; j<cnt; j+=32){
            int eid = g_csr[b+j];
#pragma unroll
            for(int h=0;h<4;h++) su[h] += __expf(g_logits[eid*4+h] - mx[h]);
        }
#pragma unroll
        for(int h=0;h<4;h++)
            for(int o=16;o;o>>=1) su[h] += __shfl_xor_sync(0xffffffffu, su[h], o);
        if(lane < 4){ sm4[lane] = mx[lane]; sinv[lane] = 1.f/(su[lane] + 1e-16f); }
    }
    __syncthreads();

    float a0=0.f, a1=0.f, a2=0.f, a3=0.f;
    int c = tid, h = c>>6;
    for(int base=0; base<cnt; base+=32){
        int jn = min(32, cnt-base);
        if(tid < 32 && lane < jn){
            int eid = g_csr[b+base+lane];
            sS[lane] = (eid < Ee) ? src[eid] : n;
#pragma unroll
            for(int hh=0; hh<4; hh++)
                sA[lane*4+hh] = __expf(g_logits[eid*4+hh] - sm4[hh]) * sinv[hh];
        }
        __syncthreads();
        int j = 0;
        for(; j+4<=jn; j+=4){
            a0 += sA[(j+0)*4+h] * xl[(size_t)sS[j+0]*LDB + c];
            a1 += sA[(j+1)*4+h] * xl[(size_t)sS[j+1]*LDB + c];
            a2 += sA[(j+2)*4+h] * xl[(size_t)sS[j+2]*LDB + c];
            a3 += sA[(j+3)*4+h] * xl[(size_t)sS[j+3]*LDB + c];
        }
        for(; j<jn; j++)
            a0 += sA[j*4+h] * xl[(size_t)sS[j]*LDB + c];
        __syncthreads();
    }
    float acc = (a0+a1)+(a2+a3);

    float v = siluf(acc + bias[c]);
    float s1 = v, s2 = v*v;
    for(int o=16;o;o>>=1){ s1 += __shfl_xor_sync(0xffffffffu,s1,o); s2 += __shfl_xor_sync(0xffffffffu,s2,o); }
    if(lane == 0){ red[warp] = s1; red[8+warp] = s2; }
    __syncthreads();
    if(warp == 0){
        float a = (lane<8)? red[lane]   : 0.f;
        float q = (lane<8)? red[8+lane] : 0.f;
        for(int o=4;o;o>>=1){ a += __shfl_xor_sync(0xffffffffu,a,o); q += __shfl_xor_sync(0xffffffffu,q,o); }
        if(lane == 0){ red[0]=a; red[8]=q; }
    }
    __syncthreads();
    float mu  = red[0]*(1.f/256.f);
    float var = red[8]*(1.f/256.f) - mu*mu;
    out[(size_t)n*1024 + c] = (v-mu)*rsqrtf(var+1e-5f)*ln1s[c] + ln1b[c];
}

// ---------------- per-graph pooling + head ----------------
__global__ void k_pool(const int* __restrict__ batch, const float* __restrict__ hW,
                       const float* __restrict__ hb, float* __restrict__ out){
    __shared__ int bnd[2];
    __shared__ float red[8];
    __shared__ float sstat[2];
    int g = blockIdx.x, tid = threadIdx.x, lane = tid&31, warp = tid>>5;
    if(tid < 2){
        int tgt = g + tid;
        int lo=0, hi=Nn;
        while(lo<hi){ int m=(lo+hi)>>1; if(batch[m]<tgt) lo=m+1; else hi=m; }
        bnd[tid]=lo;
    }
    __syncthreads();
    int lo=bnd[0], hi=bnd[1];

    float m = -1e30f;
    for(int i=lo+tid;i<hi;i+=256) m = fmaxf(m, g_gate[i]);
    for(int o=16;o;o>>=1) m = fmaxf(m, __shfl_xor_sync(0xffffffffu,m,o));
    if(lane==0) red[warp]=m;
    __syncthreads();
    if(tid==0){
        float v=red[0];
        for(int w2=1;w2<8;w2++) v = fmaxf(v, red[w2]);
        if(v < -1e29f) v = 0.f;
        sstat[0]=v;
    }
    __syncthreads();
    m = sstat[0];
    float sd = 0.f;
    for(int i=lo+tid;i<hi;i+=256) sd += __expf(g_gate[i]-m);
    for(int o=16;o;o>>=1) sd += __shfl_xor_sync(0xffffffffu,sd,o);
    if(lane==0) red[warp]=sd;
    __syncthreads();
    if(tid==0){
        float v=0.f;
        for(int w2=0;w2<8;w2++) v += red[w2];
        sstat[1] = 1.f/(v+1e-16f);
    }
    __syncthreads();
    float inv = sstat[1];
    float acc = 0.f;
    for(int i=lo;i<hi;i++){
        float w2 = __expf(g_gate[i]-m)*inv;
        acc += w2 * g_hfin[(size_t)i*256+tid];
    }
    float pv = acc*hW[tid];
    for(int o=16;o;o>>=1) pv += __shfl_xor_sync(0xffffffffu,pv,o);
    if(lane==0) red[warp]=pv;
    __syncthreads();
    if(tid==0){
        float v=0.f;
        for(int w2=0;w2<8;w2++) v += red[w2];
        out[g] = v + hb[0];
    }
}

// ---------------- host ----------------
extern "C" void kernel_launch(void* const* d_in, const int* in_sizes, int n_in,
                              void* d_out, int out_size){
    const float* x     = (const float*)d_in[0];
    const int*   ei    = (const int*)  d_in[1];
    const float* eattr = (const float*)d_in[2];
    const int*   batch = (const int*)  d_in[3];
    const float* atomW = (const float*)d_in[4];
    const float* atomB = (const float*)d_in[5];
    const float* bondW = (const float*)d_in[6];
    const float* bondB = (const float*)d_in[7];
    const float* Wl    = (const float*)d_in[8];
    const float* bl    = (const float*)d_in[9];
    const float* Wr    = (const float*)d_in[10];
    const float* br    = (const float*)d_in[11];
    const float* We    = (const float*)d_in[12];
    const float* att   = (const float*)d_in[13];
    const float* bias  = (const float*)d_in[14];
    const float* ln1s  = (const float*)d_in[15];
    const float* ln1b  = (const float*)d_in[16];
    const float* eW    = (const float*)d_in[17];
    const float* eb    = (const float*)d_in[18];
    const float* ln2s  = (const float*)d_in[19];
    const float* ln2b  = (const float*)d_in[20];
    const float* jkW   = (const float*)d_in[21];
    const float* jkb   = (const float*)d_in[22];
    const float* ln3s  = (const float*)d_in[23];
    const float* ln3b  = (const float*)d_in[24];
    const float* gW1   = (const float*)d_in[25];
    const float* gb1   = (const float*)d_in[26];
    const float* gW2   = (const float*)d_in[27];
    const float* gb2   = (const float*)d_in[28];
    const float* hW    = (const float*)d_in[29];
    const float* hb    = (const float*)d_in[30];
    float* out = (float*)d_out;

    const int* src = ei;
    const int* dst = ei + Ee;

    float *h0p, *eAp, *eBp, *bigp, *pqp, *hjkp, *hfinp, *logp, *wpk, *bpk, *wpq;
    int *srcxp, *dstxp;
    cudaGetSymbolAddress((void**)&h0p,   g_h0);
    cudaGetSymbolAddress((void**)&eAp,   g_eA);
    cudaGetSymbolAddress((void**)&eBp,   g_eB);
    cudaGetSymbolAddress((void**)&bigp,  g_big);
    cudaGetSymbolAddress((void**)&pqp,   g_pq);
    cudaGetSymbolAddress((void**)&hjkp,  g_hjk);
    cudaGetSymbolAddress((void**)&hfinp, g_hfin);
    cudaGetSymbolAddress((void**)&logp,  g_logits);
    cudaGetSymbolAddress((void**)&wpk,   g_wpack);
    cudaGetSymbolAddress((void**)&bpk,   g_bpack);
    cudaGetSymbolAddress((void**)&wpq,   g_wpq);
    cudaGetSymbolAddress((void**)&srcxp, g_srcx);
    cudaGetSymbolAddress((void**)&dstxp, g_dstx);

    static cudaStream_t s2 = nullptr;
    static cudaEvent_t evFork, evP, evCSR, evL[4], evA[3];
    if(!s2){
        cudaStreamCreateWithFlags(&s2, cudaStreamNonBlocking);
        cudaEventCreateWithFlags(&evFork, cudaEventDisableTiming);
        cudaEventCreateWithFlags(&evP,    cudaEventDisableTiming);
        cudaEventCreateWithFlags(&evCSR,  cudaEventDisableTiming);
        for(int i=0;i<4;i++) cudaEventCreateWithFlags(&evL[i], cudaEventDisableTiming);
        for(int i=0;i<3;i++) cudaEventCreateWithFlags(&evA[i], cudaEventDisableTiming);
    }

    // ---- fork s2 off the main (captured) stream ----
    cudaEventRecord(evFork, 0);
    cudaStreamWaitEvent(s2, evFork, 0);

    // s2: encoders + weight packing + extidx
    k_atom_enc<<<(Nn*Dd+255)/256,256,0,s2>>>(x, atomW, atomB);
    k_bond_enc<<<(Ee*EDd+255)/256,256,0,s2>>>(eattr, bondW, bondB);
    k_pack<<<(4*Dd*LDB+255)/256,256,0,s2>>>(Wl, Wr);
    k_packpq<<<(4*Dd*128+255)/256,256,0,s2>>>(eW);
    k_packb<<<(4*LDB+255)/256,256,0,s2>>>(bl, br);
    k_extidx<<<(ENt+255)/256,256,0,s2>>>(src, dst);
    cudaEventRecord(evP, s2);

    // s1: CSR build (multi-block scan)
    k_zero_deg<<<(Nn+255)/256,256>>>();
    k_deg <<<(Ee+255)/256,256>>>(dst);
    k_scan_local<<<20,1024>>>();
    k_scan_off<<<1,32>>>();
    k_scan_add<<<(Nn+255)/256,256>>>();
    k_fill<<<(Ee+255)/256,256>>>(dst);
    k_selfloop<<<(Nn+255)/256,256>>>();
    cudaEventRecord(evCSR, 0);

    // s2: loope(0)
    cudaStreamWaitEvent(s2, evCSR, 0);
    k_loope<<<Nn,64,0,s2>>>(eAp);
    cudaEventRecord(evL[0], s2);

    cudaStreamWaitEvent(0, evP, 0);

    for(int l=0; l<4; l++){
        float* e_cur  = (l&1) ? eBp : eAp;
        float* e_next = (l&1) ? eAp : eBp;
        const float* hcur = (l==0) ? h0p : (hjkp + (l-1)*256);
        int ldh = (l==0) ? 256 : 1024;

        // s1: packed node GEMM [xl|xr] = hcur @ [Wl|Wr]
        dim3 gN(LDB/128, (Nn+127)/128);
        mma_gemm<128,128,16,64,32,0,0><<<gN,256>>>(
            hcur, ldh, wpk + l*Dd*LDB, LDB, bpk + l*LDB, bigp, LDB, Nn, 256,
            nullptr,nullptr,nullptr,nullptr, nullptr,nullptr, 0);

        cudaStreamWaitEvent(0, evL[l], 0);

        // s1: logits
        dim3 gL(2,(ENt+127)/128);
        mma_gemm<128,128,16,64,32,1,3><<<gL,256>>>(
            e_cur, 64, We + l*EDd*Dd, 256, nullptr, logp, 4, ENt, 64,
            bigp, bigp + 256, srcxp, dstxp, att + l*256, nullptr, LDB);

        // s1: aggregate
        k_aggregate<<<Nn,256>>>(src, bigp, bias + l*256, ln1s + l*256, ln1b + l*256,
                                hjkp + l*256);

        if(l < 3){
            cudaEventRecord(evA[l], 0);
            // s2: edge path
            cudaStreamWaitEvent(s2, evA[l], 0);
            dim3 gPQ(1,(Nn+127)/128);
            mma_gemm<128,128,16,64,32,0,0><<<gPQ,256,0,s2>>>(
                hjkp + l*256, 1024, wpq + l*Dd*128, 128, nullptr, pqp, 128, Nn, 256,
                nullptr,nullptr,nullptr,nullptr, nullptr,nullptr, 0);
            dim3 gE(1, Ee/128);
            mma_gemm<128,64,16,32,32,0,4><<<gE,256,0,s2>>>(
                e_cur, 64, eW + l*576*64 + 512*64, 64, eb + l*64, e_next, 64, Ee, 64,
                pqp, nullptr, src, dst, ln2s + l*64, ln2b + l*64, 128);
            k_loope<<<Nn,64,0,s2>>>(e_next);
            cudaEventRecord(evL[l+1], s2);
        }
    }

    // tail on s1: JK GEMM with fused silu+LN(256) epilogue (full-row blocks)
    dim3 gJK(1,(Nn+63)/64);
    mma_gemm<64,256,16,32,64,0,7><<<gJK,256>>>(
        hjkp, 1024, jkW, 256, jkb, hfinp, 256, Nn, 1024,
        nullptr,nullptr,nullptr,nullptr, ln3s, ln3b, 0);

    dim3 gG1(1,(Nn+127)/128);
    mma_gemm<128,128,16,64,32,0,5><<<gG1,256>>>(
        hfinp, 256, gW1, 128, gb1, nullptr, 0, Nn, 256,
        nullptr,nullptr,nullptr,nullptr, gW2, gb2, 0);

    k_pool<<<Gg,256>>>(batch, hW, hb, out);
}